// round 7
// baseline (speedup 1.0000x reference)
#include <cuda_runtime.h>
#include <math.h>

#define NB 32
#define NL 128
#define ND 300
#define NH 1024
#define G4 4096
#define G6 6144
#define K3 3072
#define KIH 320          // D padded to multiple of 32
#define MAXLVL 128
#define MAXPERLVL 2048   // per level, <=64 ops/batch * 32 batches

// -------------------- scratch (device globals: the sanctioned workaround) ---
__device__ float g_WtIh[KIH * G4];        // [k][j], rows >= 300 zero
__device__ float g_WtHh[NH * G4];         // [k][j]
__device__ float g_WtComp[K3 * G6];       // [k][j]
__device__ float g_Xg[(NB * NL) * G4];    // x@W_ih^T + b_ih + b_hh
__device__ float g_hs[NB * NL * NH];
__device__ float g_cs[NB * NL * NH];
__device__ float g_nh[NB * NL * NH];      // internal node h
__device__ float g_nc[NB * NL * NH];      // internal node c
__device__ int   g_ops[NB * NL * 4];      // per-batch ops: x, lcode, rcode, lvl
__device__ int   g_nops[NB];
__device__ int   g_root[NB];              // global code of root
__device__ int   g_lvlcnt[MAXLVL];
__device__ int   g_list[MAXLVL * MAXPERLVL * 4]; // dst, xglob, lglob, rglob

__device__ __forceinline__ float sigf(float x) { return 1.f / (1.f + expf(-x)); }

// -------------------- transpose W[N][K] -> Wt[Kp][N], zero-pad k in [K,Kp) --
__global__ void transposeK(const float* __restrict__ W, float* __restrict__ Wt,
                           int N, int K, int Kp) {
    __shared__ float tile[32][33];
    int j0 = blockIdx.x * 32, k0 = blockIdx.y * 32;
    int tx = threadIdx.x, ty = threadIdx.y;
    for (int r = ty; r < 32; r += 8) {
        int j = j0 + r, k = k0 + tx;
        tile[r][tx] = (j < N && k < K) ? W[(size_t)j * K + k] : 0.f;
    }
    __syncthreads();
    for (int r = ty; r < 32; r += 8) {
        int k = k0 + r, j = j0 + tx;
        if (k < Kp && j < N) Wt[(size_t)k * N + j] = tile[tx][r];
    }
}

// -------------------- Xg[m][n] = x[m,:] . WtIh[:,n] + b_ih[n] + b_hh[n] -----
__global__ __launch_bounds__(256) void xg_gemm(const float* __restrict__ x,
                                               const float* __restrict__ b_ih,
                                               const float* __restrict__ b_hh) {
    __shared__ float Xs[32][33];
    __shared__ float Ws[32][32];
    int tx = threadIdx.x, ty = threadIdx.y;
    int n0 = blockIdx.x * 32, m0 = blockIdx.y * 32;
    float a0 = 0.f, a1 = 0.f, a2 = 0.f, a3 = 0.f;
    for (int k0 = 0; k0 < KIH; k0 += 32) {
#pragma unroll
        for (int p = 0; p < 4; p++) {
            int r = ty + p * 8;
            int k = k0 + tx;
            Xs[r][tx] = (k < ND) ? x[(size_t)(m0 + r) * ND + k] : 0.f;
            Ws[r][tx] = g_WtIh[(size_t)(k0 + r) * G4 + n0 + tx];
        }
        __syncthreads();
#pragma unroll
        for (int kk = 0; kk < 32; kk++) {
            float xv = Xs[tx][kk];
            float4 w = *(const float4*)&Ws[kk][ty * 4];
            a0 = fmaf(xv, w.x, a0); a1 = fmaf(xv, w.y, a1);
            a2 = fmaf(xv, w.z, a2); a3 = fmaf(xv, w.w, a3);
        }
        __syncthreads();
    }
    int m = m0 + tx;
    int n = n0 + ty * 4;
    float4 o;
    o.x = a0 + b_ih[n + 0] + b_hh[n + 0];
    o.y = a1 + b_ih[n + 1] + b_hh[n + 1];
    o.z = a2 + b_ih[n + 2] + b_hh[n + 2];
    o.w = a3 + b_ih[n + 3] + b_hh[n + 3];
    *(float4*)&g_Xg[(size_t)m * G4 + n] = o;
}

// -------------------- one recurrent LSTM step (fused GEMM + cell) ----------
// grid: 128 blocks (8 hidden units each); threads (32 batch, 8 jh)
__global__ __launch_bounds__(256) void lstm_step(int t) {
    __shared__ float Hs[32][33];
    __shared__ float Ws[32][32];     // [kk][jl*4 + g]
    int tx = threadIdx.x, ty = threadIdx.y;
    int j0 = blockIdx.x * 8;
    int b = tx, jh = j0 + ty;
    size_t xbase = (size_t)(b * NL + t) * G4 + jh;
    float a0 = g_Xg[xbase + 0 * NH];
    float a1 = g_Xg[xbase + 1 * NH];
    float a2 = g_Xg[xbase + 2 * NH];
    float a3 = g_Xg[xbase + 3 * NH];
    if (t > 0) {
        int gsel = tx >> 3, jl = tx & 7;
        for (int k0 = 0; k0 < NH; k0 += 32) {
#pragma unroll
            for (int p = 0; p < 4; p++) {
                int r = ty + p * 8;
                Hs[r][tx] = g_hs[(size_t)(r * NL + (t - 1)) * NH + k0 + tx];
                Ws[r][jl * 4 + gsel] =
                    g_WtHh[(size_t)(k0 + r) * G4 + gsel * NH + j0 + jl];
            }
            __syncthreads();
#pragma unroll
            for (int kk = 0; kk < 32; kk++) {
                float hv = Hs[tx][kk];
                float4 w = *(const float4*)&Ws[kk][ty * 4];
                a0 = fmaf(hv, w.x, a0); a1 = fmaf(hv, w.y, a1);
                a2 = fmaf(hv, w.z, a2); a3 = fmaf(hv, w.w, a3);
            }
            __syncthreads();
        }
    }
    float cprev = (t > 0) ? g_cs[(size_t)(b * NL + (t - 1)) * NH + jh] : 0.f;
    float c = sigf(a1) * cprev + sigf(a0) * tanhf(a2);
    float h = sigf(a3) * tanhf(c);
    g_hs[(size_t)(b * NL + t) * NH + jh] = h;
    g_cs[(size_t)(b * NL + t) * NH + jh] = c;
}

// -------------------- tree schedule: per-batch greedy build -----------------
__global__ void schedule(const int* __restrict__ words, const int* __restrict__ lens) {
    int b = threadIdx.x;
    for (int i = b; i < MAXLVL; i += 32) g_lvlcnt[i] = 0;
    if (b >= NB) return;
    int len = lens[b];
    if (len > NL) len = NL;
    if (len < 0) len = 0;
    int keys[NL];
    for (int l = 0; l < len; l++) keys[l] = words[b * NL + l] % 1000;
    int oplv[NL];
    // explicit stack: child codes: -1 none, [0,128) leaf pos, 1000+idx node
    int st_s[NL + 4], st_e[NL + 4], st_p[NL + 4], st_st[NL + 4], st_l[NL + 4];
    int sp = 0;
    st_s[0] = 0; st_e[0] = len; st_st[0] = 0; sp = 1;
    int ret = -1, nops = 0;
    while (sp > 0) {
        int i = sp - 1;
        int stage = st_st[i];
        if (stage == 0) {
            int s = st_s[i], e = st_e[i];
            if (e <= s)            { ret = -1; sp--; }
            else if (e == s + 1)   { ret = s;  sp--; }
            else {
                int bk = 0x7fffffff, bp = s;
                for (int l = s; l < e; l++)
                    if (keys[l] < bk) { bk = keys[l]; bp = l; }
                st_p[i] = bp; st_st[i] = 1;
                st_s[sp] = s; st_e[sp] = bp; st_st[sp] = 0; sp++;
            }
        } else if (stage == 1) {
            st_l[i] = ret; st_st[i] = 2;
            st_s[sp] = st_p[i] + 1; st_e[sp] = st_e[i]; st_st[sp] = 0; sp++;
        } else {
            int li = st_l[i], ri = ret;
            int ll = (li >= 1000) ? oplv[li - 1000] : 0;
            int rl = (ri >= 1000) ? oplv[ri - 1000] : 0;
            int lvl = 1 + (ll > rl ? ll : rl);
            int idx = nops++;
            oplv[idx] = lvl;
            int base = (b * NL + idx) * 4;
            g_ops[base + 0] = st_p[i];
            g_ops[base + 1] = li;
            g_ops[base + 2] = ri;
            g_ops[base + 3] = lvl;
            ret = 1000 + idx; sp--;
        }
    }
    g_nops[b] = nops;
    int root;
    if (ret >= 1000)      root = 4096 + b * NL + (ret - 1000);
    else if (ret >= 0)    root = b * NL + ret;
    else                  root = -1;
    g_root[b] = root;
}

// -------------------- bucket ops into per-level work lists ------------------
__global__ void listbuild() {
    int b = threadIdx.x;
    if (b >= NB) return;
    int n = g_nops[b];
    for (int i = 0; i < n; i++) {
        int base = (b * NL + i) * 4;
        int xp  = g_ops[base + 0];
        int li  = g_ops[base + 1];
        int ri  = g_ops[base + 2];
        int lvl = g_ops[base + 3];
        if (lvl >= MAXLVL) lvl = MAXLVL - 1;
        int slot = atomicAdd(&g_lvlcnt[lvl], 1);
        if (slot < MAXPERLVL) {
            int lb = (lvl * MAXPERLVL + slot) * 4;
            g_list[lb + 0] = b * NL + i;       // dst node slot
            g_list[lb + 1] = b * NL + xp;      // x leaf (global)
            g_list[lb + 2] = (li < 0) ? -1 : (li < 1000 ? b * NL + li
                                                        : 4096 + b * NL + (li - 1000));
            g_list[lb + 3] = (ri < 0) ? -1 : (ri < 1000 ? b * NL + ri
                                                        : 4096 + b * NL + (ri - 1000));
        }
    }
}

// -------------------- one compose level: fused batched GEMV + cell ----------
// grid: (64 lane-groups, 128 jh tiles); threads (32 lanes, 8 jh)
__global__ __launch_bounds__(256) void compose_level(int lvl,
                                                     const float* __restrict__ b_comp) {
    int cnt = g_lvlcnt[lvl];
    if (cnt > MAXPERLVL) cnt = MAXPERLVL;
    if ((int)(blockIdx.x * 32) >= cnt) return;
    __shared__ float Hs[32][33];
    __shared__ float Ws[32 * 64];          // [kk][jl*8 + g], 6 used + 2 pad
    __shared__ int s_dst[32], s_x[32], s_l[32], s_r[32];
    int tx = threadIdx.x, ty = threadIdx.y;
    int tid = ty * 32 + tx;
    if (tid < 32) {
        int rl = blockIdx.x * 32 + tid;
        if (rl > cnt - 1) rl = cnt - 1;
        const int* rec = g_list + ((size_t)lvl * MAXPERLVL + rl) * 4;
        s_dst[tid] = rec[0]; s_x[tid] = rec[1];
        s_l[tid]   = rec[2]; s_r[tid] = rec[3];
    }
    __syncthreads();
    int j0 = blockIdx.y * 8;
    float a0 = 0.f, a1 = 0.f, a2 = 0.f, a3 = 0.f, a4 = 0.f, a5 = 0.f;
    for (int k0 = 0; k0 < K3; k0 += 32) {
        int seg = k0 >> 10, off = k0 & 1023;
#pragma unroll
        for (int p = 0; p < 4; p++) {
            int r = ty + p * 8;
            int code = (seg == 0) ? s_l[r] : ((seg == 1) ? s_x[r] : s_r[r]);
            float v = 0.f;
            if (code >= 0) {
                const float* hp = (code < 4096)
                    ? (g_hs + (size_t)code * NH)
                    : (g_nh + (size_t)(code - 4096) * NH);
                v = hp[off + tx];
            }
            Hs[r][tx] = v;
        }
        for (int idx = tid; idx < 32 * 48; idx += 256) {
            int kk = idx / 48, col = idx - kk * 48;
            int g = col >> 3, jl = col & 7;
            Ws[kk * 64 + jl * 8 + g] =
                g_WtComp[(size_t)(k0 + kk) * G6 + g * NH + j0 + jl];
        }
        __syncthreads();
#pragma unroll
        for (int kk = 0; kk < 32; kk++) {
            float hv = Hs[tx][kk];
            float4 wA = *(const float4*)&Ws[kk * 64 + ty * 8];
            float2 wB = *(const float2*)&Ws[kk * 64 + ty * 8 + 4];
            a0 = fmaf(hv, wA.x, a0); a1 = fmaf(hv, wA.y, a1);
            a2 = fmaf(hv, wA.z, a2); a3 = fmaf(hv, wA.w, a3);
            a4 = fmaf(hv, wB.x, a4); a5 = fmaf(hv, wB.y, a5);
        }
        __syncthreads();
    }
    int lane = blockIdx.x * 32 + tx;
    if (lane < cnt) {
        int jh = j0 + ty;
        a0 += b_comp[0 * NH + jh]; a1 += b_comp[1 * NH + jh];
        a2 += b_comp[2 * NH + jh]; a3 += b_comp[3 * NH + jh];
        a4 += b_comp[4 * NH + jh]; a5 += b_comp[5 * NH + jh];
        int cL = s_l[tx], cX = s_x[tx], cR = s_r[tx];
        float cl = 0.f, cx = 0.f, cr = 0.f;
        if (cL >= 0) cl = (cL < 4096) ? g_cs[(size_t)cL * NH + jh]
                                      : g_nc[(size_t)(cL - 4096) * NH + jh];
        if (cX >= 0) cx = (cX < 4096) ? g_cs[(size_t)cX * NH + jh]
                                      : g_nc[(size_t)(cX - 4096) * NH + jh];
        if (cR >= 0) cr = (cR < 4096) ? g_cs[(size_t)cR * NH + jh]
                                      : g_nc[(size_t)(cR - 4096) * NH + jh];
        float c = sigf(a0) * tanhf(a4) + sigf(a1) * cl + sigf(a2) * cx + sigf(a3) * cr;
        float h = sigf(a5) * tanhf(c);
        int dst = s_dst[tx];
        g_nh[(size_t)dst * NH + jh] = h;
        g_nc[(size_t)dst * NH + jh] = c;
    }
}

// -------------------- gather roots into output ------------------------------
__global__ void gather_out(float* __restrict__ out) {
    int idx = blockIdx.x * blockDim.x + threadIdx.x;  // 0..32767
    int b = idx >> 10, j = idx & (NH - 1);
    int code = g_root[b];
    float h = 0.f, c = 0.f;
    if (code >= 0) {
        if (code < 4096) {
            h = g_hs[(size_t)code * NH + j];
            c = g_cs[(size_t)code * NH + j];
        } else {
            int n = code - 4096;
            h = g_nh[(size_t)n * NH + j];
            c = g_nc[(size_t)n * NH + j];
        }
    }
    out[idx] = h;
    out[NB * NH + idx] = c;
}

// -------------------- launcher ---------------------------------------------
extern "C" void kernel_launch(void* const* d_in, const int* in_sizes, int n_in,
                              void* d_out, int out_size) {
    const float* x      = (const float*)d_in[0];  // (32,128,300)
    const float* W_ih   = (const float*)d_in[1];  // (4096,300)
    const float* W_hh   = (const float*)d_in[2];  // (4096,1024)
    const float* b_ih   = (const float*)d_in[3];  // (4096)
    const float* b_hh   = (const float*)d_in[4];  // (4096)
    const float* W_comp = (const float*)d_in[5];  // (6144,3072)
    const float* b_comp = (const float*)d_in[6];  // (6144)
    const int*   words  = (const int*)d_in[7];    // (32,128)
    const int*   lens   = (const int*)d_in[8];    // (32)
    float* out = (float*)d_out;

    void *pWtIh = 0, *pWtHh = 0, *pWtComp = 0;
    cudaGetSymbolAddress(&pWtIh, g_WtIh);
    cudaGetSymbolAddress(&pWtHh, g_WtHh);
    cudaGetSymbolAddress(&pWtComp, g_WtComp);

    dim3 thr(32, 8);
    transposeK<<<dim3(128, 10), thr>>>(W_ih, (float*)pWtIh, G4, ND, KIH);
    transposeK<<<dim3(128, 32), thr>>>(W_hh, (float*)pWtHh, G4, NH, NH);
    transposeK<<<dim3(192, 96), thr>>>(W_comp, (float*)pWtComp, G6, K3, K3);

    xg_gemm<<<dim3(128, 128), thr>>>(x, b_ih, b_hh);

    schedule<<<1, 32>>>(words, lens);
    listbuild<<<1, 32>>>();

    for (int t = 0; t < NL; t++)
        lstm_step<<<128, thr>>>(t);

    for (int lvl = 1; lvl < MAXLVL; lvl++)
        compose_level<<<dim3(64, 128), thr>>>(lvl, b_comp);

    gather_out<<<64, 512>>>(out);
}

// round 9
// speedup vs baseline: 1.7241x; 1.7241x over previous
#include <cuda_runtime.h>
#include <math.h>

#define NB 32
#define NL 128
#define ND 300
#define NH 1024
#define G4 4096
#define G6 6144
#define K3 3072
#define KIH 320          // D padded to multiple of 32
#define MAXLVL 48
#define MAXPERLVL 2048   // per level, <=64 ops/batch * 32 batches

// -------------------- scratch (device globals) ------------------------------
__device__ float g_WtIh[KIH * G4];        // [k][j], rows >= 300 zero
__device__ float g_WtHh[NH * G4];         // [k][colperm] (lstm interleaved layout)
__device__ float g_WtComp[K3 * G6];       // [k][j]
__device__ float g_Xg[(NB * NL) * G4];    // x@W_ih^T + b_ih + b_hh
__device__ float g_hs[NB * NL * NH];
__device__ float g_cs[NB * NL * NH];
__device__ float g_nh[NB * NL * NH];      // internal node h
__device__ float g_nc[NB * NL * NH];      // internal node c
__device__ float g_part[3 * MAXPERLVL * G6]; // split-K partials (per child seg)
__device__ int   g_ops[NB * NL * 4];
__device__ int   g_nops[NB];
__device__ int   g_root[NB];
__device__ int   g_lvlcnt[MAXLVL];
__device__ int   g_list[MAXLVL * MAXPERLVL * 4]; // dst, xglob, lglob, rglob

__device__ __forceinline__ float sigf(float x) { return 1.f / (1.f + expf(-x)); }

// -------------------- transpose W[N][K] -> Wt[Kp][N], zero-pad k in [K,Kp) --
__global__ void transposeK(const float* __restrict__ W, float* __restrict__ Wt,
                           int N, int K, int Kp) {
    __shared__ float tile[32][33];
    int j0 = blockIdx.x * 32, k0 = blockIdx.y * 32;
    int tx = threadIdx.x, ty = threadIdx.y;
    for (int r = ty; r < 32; r += 8) {
        int j = j0 + r, k = k0 + tx;
        tile[r][tx] = (j < N && k < K) ? W[(size_t)j * K + k] : 0.f;
    }
    __syncthreads();
    for (int r = ty; r < 32; r += 8) {
        int k = k0 + r, j = j0 + tx;
        if (k < Kp && j < N) Wt[(size_t)k * N + j] = tile[tx][r];
    }
}

// -------------------- W_hh -> k-major with lstm-interleaved columns ---------
// out col' = (jh>>3)*32 + (jh&7)*4 + gate  (so a block's 32 cols are contiguous
// and land in smem as [kk][jl*4+gate] with a straight copy)
__global__ void transposeWhh(const float* __restrict__ W) {
    int row = blockIdx.x;                    // 0..4095 = gate*1024 + jh
    int gate = row >> 10, jh = row & 1023;
    int colp = ((jh >> 3) << 5) + ((jh & 7) << 2) + gate;
    const float* src = W + (size_t)row * NH;
    for (int k = threadIdx.x; k < NH; k += 256)
        g_WtHh[(size_t)k * G4 + colp] = src[k];
}

// -------------------- Xg = x @ WtIh + b_ih + b_hh : 128x128x16 sgemm -------
__global__ __launch_bounds__(256) void xg_gemm(const float* __restrict__ x,
                                               const float* __restrict__ b_ih,
                                               const float* __restrict__ b_hh) {
    __shared__ float As[16][132];   // [kk][m]
    __shared__ float Bs[16][128];   // [kk][n]
    int tid = threadIdx.x;
    int tx = tid & 15, ty = tid >> 4;
    int n0 = blockIdx.x * 128, m0 = blockIdx.y * 128;
    float acc[64];
#pragma unroll
    for (int i = 0; i < 64; i++) acc[i] = 0.f;

    for (int k0 = 0; k0 < KIH; k0 += 16) {
        __syncthreads();
        {   // A: 128 rows x 16 k (gathered from x, k guard at 300)
            int r = tid >> 1;
            int kb = (tid & 1) * 8;
            const float* xr = x + (size_t)(m0 + r) * ND + k0 + kb;
#pragma unroll
            for (int i = 0; i < 8; i++) {
                int k = k0 + kb + i;
                As[kb + i][r] = (k < ND) ? xr[i] : 0.f;
            }
            // B: 16 rows x 128 cols
            int br = tid >> 4, bc = (tid & 15) * 8;
            const float* wb = g_WtIh + (size_t)(k0 + br) * G4 + n0 + bc;
            *(float4*)&Bs[br][bc]     = *(const float4*)(wb);
            *(float4*)&Bs[br][bc + 4] = *(const float4*)(wb + 4);
        }
        __syncthreads();
#pragma unroll
        for (int kk = 0; kk < 16; kk++) {
            float4 a0 = *(const float4*)&As[kk][ty * 4];
            float4 a1 = *(const float4*)&As[kk][64 + ty * 4];
            float4 b0 = *(const float4*)&Bs[kk][tx * 4];
            float4 b1 = *(const float4*)&Bs[kk][64 + tx * 4];
            float av[8] = {a0.x, a0.y, a0.z, a0.w, a1.x, a1.y, a1.z, a1.w};
            float bv[8] = {b0.x, b0.y, b0.z, b0.w, b1.x, b1.y, b1.z, b1.w};
#pragma unroll
            for (int i = 0; i < 8; i++)
#pragma unroll
                for (int j = 0; j < 8; j++)
                    acc[i * 8 + j] = fmaf(av[i], bv[j], acc[i * 8 + j]);
        }
    }
#pragma unroll
    for (int hm = 0; hm < 2; hm++)
#pragma unroll
        for (int i = 0; i < 4; i++) {
            int m = m0 + hm * 64 + ty * 4 + i;
            float* orow = g_Xg + (size_t)m * G4 + n0;
#pragma unroll
            for (int hn = 0; hn < 2; hn++) {
                int nb = hn * 64 + tx * 4;
                int ai = (hm * 4 + i) * 8 + hn * 4;
                float4 v;
                v.x = acc[ai + 0] + b_ih[n0 + nb + 0] + b_hh[n0 + nb + 0];
                v.y = acc[ai + 1] + b_ih[n0 + nb + 1] + b_hh[n0 + nb + 1];
                v.z = acc[ai + 2] + b_ih[n0 + nb + 2] + b_hh[n0 + nb + 2];
                v.w = acc[ai + 3] + b_ih[n0 + nb + 3] + b_hh[n0 + nb + 3];
                *(float4*)&orow[nb] = v;
            }
        }
}

// -------------------- one recurrent LSTM step (fused GEMM + cell) ----------
// grid: 128 blocks (8 hidden units each); threads (32 batch, 8 jh)
__global__ __launch_bounds__(256) void lstm_step(int t) {
    __shared__ float Hs[32][33];
    __shared__ float Ws[32][32];     // [kk][jl*4 + gate]
    int tx = threadIdx.x, ty = threadIdx.y;
    int j0 = blockIdx.x * 8;
    int b = tx, jh = j0 + ty;
    size_t xbase = (size_t)(b * NL + t) * G4 + jh;
    float a0 = g_Xg[xbase + 0 * NH];
    float a1 = g_Xg[xbase + 1 * NH];
    float a2 = g_Xg[xbase + 2 * NH];
    float a3 = g_Xg[xbase + 3 * NH];
    if (t > 0) {
        int cb = blockIdx.x << 5;    // permuted col base
        for (int k0 = 0; k0 < NH; k0 += 32) {
#pragma unroll
            for (int p = 0; p < 4; p++) {
                int r = ty + p * 8;
                Hs[r][tx] = g_hs[(size_t)(r * NL + (t - 1)) * NH + k0 + tx];
                Ws[r][tx] = g_WtHh[(size_t)(k0 + r) * G4 + cb + tx];
            }
            __syncthreads();
#pragma unroll
            for (int kk = 0; kk < 32; kk++) {
                float hv = Hs[tx][kk];
                float4 w = *(const float4*)&Ws[kk][ty * 4];
                a0 = fmaf(hv, w.x, a0); a1 = fmaf(hv, w.y, a1);
                a2 = fmaf(hv, w.z, a2); a3 = fmaf(hv, w.w, a3);
            }
            __syncthreads();
        }
    }
    float cprev = (t > 0) ? g_cs[(size_t)(b * NL + (t - 1)) * NH + jh] : 0.f;
    float c = sigf(a1) * cprev + sigf(a0) * tanhf(a2);
    float h = sigf(a3) * tanhf(c);
    g_hs[(size_t)(b * NL + t) * NH + jh] = h;
    g_cs[(size_t)(b * NL + t) * NH + jh] = c;
}

// -------------------- tree schedule: per-batch greedy build -----------------
__global__ void schedule(const int* __restrict__ words, const int* __restrict__ lens) {
    int b = threadIdx.x;
    for (int i = b; i < MAXLVL; i += 32) g_lvlcnt[i] = 0;
    if (b >= NB) return;
    int len = lens[b];
    if (len > NL) len = NL;
    if (len < 0) len = 0;
    int keys[NL];
    for (int l = 0; l < len; l++) keys[l] = words[b * NL + l] % 1000;
    int oplv[NL];
    int st_s[NL + 4], st_e[NL + 4], st_p[NL + 4], st_st[NL + 4], st_l[NL + 4];
    int sp = 0;
    st_s[0] = 0; st_e[0] = len; st_st[0] = 0; sp = 1;
    int ret = -1, nops = 0;
    while (sp > 0) {
        int i = sp - 1;
        int stage = st_st[i];
        if (stage == 0) {
            int s = st_s[i], e = st_e[i];
            if (e <= s)            { ret = -1; sp--; }
            else if (e == s + 1)   { ret = s;  sp--; }
            else {
                int bk = 0x7fffffff, bp = s;
                for (int l = s; l < e; l++)
                    if (keys[l] < bk) { bk = keys[l]; bp = l; }
                st_p[i] = bp; st_st[i] = 1;
                st_s[sp] = s; st_e[sp] = bp; st_st[sp] = 0; sp++;
            }
        } else if (stage == 1) {
            st_l[i] = ret; st_st[i] = 2;
            st_s[sp] = st_p[i] + 1; st_e[sp] = st_e[i]; st_st[sp] = 0; sp++;
        } else {
            int li = st_l[i], ri = ret;
            int ll = (li >= 1000) ? oplv[li - 1000] : 0;
            int rl = (ri >= 1000) ? oplv[ri - 1000] : 0;
            int lvl = 1 + (ll > rl ? ll : rl);
            int idx = nops++;
            oplv[idx] = lvl;
            int base = (b * NL + idx) * 4;
            g_ops[base + 0] = st_p[i];
            g_ops[base + 1] = li;
            g_ops[base + 2] = ri;
            g_ops[base + 3] = lvl;
            ret = 1000 + idx; sp--;
        }
    }
    g_nops[b] = nops;
    int root;
    if (ret >= 1000)      root = 4096 + b * NL + (ret - 1000);
    else if (ret >= 0)    root = b * NL + ret;
    else                  root = -1;
    g_root[b] = root;
}

// -------------------- bucket ops into per-level work lists ------------------
__global__ void listbuild() {
    int b = threadIdx.x;
    if (b >= NB) return;
    int n = g_nops[b];
    for (int i = 0; i < n; i++) {
        int base = (b * NL + i) * 4;
        int xp  = g_ops[base + 0];
        int li  = g_ops[base + 1];
        int ri  = g_ops[base + 2];
        int lvl = g_ops[base + 3];
        if (lvl >= MAXLVL) lvl = MAXLVL - 1;
        int slot = atomicAdd(&g_lvlcnt[lvl], 1);
        if (slot < MAXPERLVL) {
            int lb = (lvl * MAXPERLVL + slot) * 4;
            g_list[lb + 0] = b * NL + i;
            g_list[lb + 1] = b * NL + xp;
            g_list[lb + 2] = (li < 0) ? -1 : (li < 1000 ? b * NL + li
                                                        : 4096 + b * NL + (li - 1000));
            g_list[lb + 3] = (ri < 0) ? -1 : (ri < 1000 ? b * NL + ri
                                                        : 4096 + b * NL + (ri - 1000));
        }
    }
}

// -------------------- compose GEMM: one level, one child segment ------------
// Computes partial[seg][op][0..6143] = h_child(seg) . WtComp[seg*1024 .. +1024]
// grid (48, 48): blockIdx.x -> (seg = bx%3, mgroup = bx/3), blockIdx.y -> n-tile.
// Block tile 32(M) x 128(N) x K=1024; 256 threads, 2x8 per thread.
__global__ __launch_bounds__(256) void compose_gemm(int lvl) {
    int cnt = g_lvlcnt[lvl];
    if (cnt > MAXPERLVL) cnt = MAXPERLVL;
    if (cnt == 0) return;
    int seg = blockIdx.x % 3, mg = blockIdx.x / 3;
    int n0 = blockIdx.y * 128;
    __shared__ float As[32][34];       // [kk][m], even pad for float2
    __shared__ float Bs[32][128];      // [kk][n]
    __shared__ int s_ch[32];
    int tid = threadIdx.x;
    int tx = tid & 15, ty = tid >> 4;
    int am = tid >> 3;                 // A-gather: lane row
    int ak = (tid & 7) * 4;            // A-gather: 4 consecutive k
    int nmt = (cnt + 31) >> 5;

    for (int mb = mg; mb < nmt; mb += 16) {
        __syncthreads();
        if (tid < 32) {
            int op = mb * 32 + tid;
            if (op > cnt - 1) op = cnt - 1;
            const int* rec = g_list + ((size_t)lvl * MAXPERLVL + op) * 4;
            s_ch[tid] = (seg == 0) ? rec[2] : ((seg == 1) ? rec[1] : rec[3]);
        }
        __syncthreads();
        int code = s_ch[am];
        const float* hp = 0;
        if (code >= 0)
            hp = (code < 4096) ? (g_hs + (size_t)code * NH)
                               : (g_nh + (size_t)(code - 4096) * NH);
        float acc0[8], acc1[8];
#pragma unroll
        for (int i = 0; i < 8; i++) { acc0[i] = 0.f; acc1[i] = 0.f; }

        for (int kt = 0; kt < 32; kt++) {
            int kb = kt * 32;
            float4 av = make_float4(0.f, 0.f, 0.f, 0.f);
            if (code >= 0) av = *(const float4*)(hp + kb + ak);
            const float* wb = g_WtComp + (size_t)(seg * NH + kb) * G6 + n0;
            int br = tid >> 5, bc = (tid & 31) * 4;
            __syncthreads();
            As[ak + 0][am] = av.x;
            As[ak + 1][am] = av.y;
            As[ak + 2][am] = av.z;
            As[ak + 3][am] = av.w;
#pragma unroll
            for (int i = 0; i < 4; i++)
                *(float4*)&Bs[br + i * 8][bc] =
                    *(const float4*)(wb + (size_t)(br + i * 8) * G6 + bc);
            __syncthreads();
#pragma unroll
            for (int kk = 0; kk < 32; kk++) {
                float2 a  = *(const float2*)&As[kk][ty * 2];
                float4 b0 = *(const float4*)&Bs[kk][tx * 4];
                float4 b1 = *(const float4*)&Bs[kk][64 + tx * 4];
                acc0[0] = fmaf(a.x, b0.x, acc0[0]); acc0[1] = fmaf(a.x, b0.y, acc0[1]);
                acc0[2] = fmaf(a.x, b0.z, acc0[2]); acc0[3] = fmaf(a.x, b0.w, acc0[3]);
                acc0[4] = fmaf(a.x, b1.x, acc0[4]); acc0[5] = fmaf(a.x, b1.y, acc0[5]);
                acc0[6] = fmaf(a.x, b1.z, acc0[6]); acc0[7] = fmaf(a.x, b1.w, acc0[7]);
                acc1[0] = fmaf(a.y, b0.x, acc1[0]); acc1[1] = fmaf(a.y, b0.y, acc1[1]);
                acc1[2] = fmaf(a.y, b0.z, acc1[2]); acc1[3] = fmaf(a.y, b0.w, acc1[3]);
                acc1[4] = fmaf(a.y, b1.x, acc1[4]); acc1[5] = fmaf(a.y, b1.y, acc1[5]);
                acc1[6] = fmaf(a.y, b1.z, acc1[6]); acc1[7] = fmaf(a.y, b1.w, acc1[7]);
            }
        }
        int m0 = mb * 32 + ty * 2;
#pragma unroll
        for (int im = 0; im < 2; im++) {
            int m = m0 + im;
            if (m < cnt) {
                float* ar = im ? acc1 : acc0;
                float* pp = g_part + ((size_t)seg * MAXPERLVL + m) * G6 + n0;
                *(float4*)&pp[tx * 4]      = make_float4(ar[0], ar[1], ar[2], ar[3]);
                *(float4*)&pp[64 + tx * 4] = make_float4(ar[4], ar[5], ar[6], ar[7]);
            }
        }
    }
}

// -------------------- compose finalize: sum partials + cell -----------------
__global__ __launch_bounds__(256) void compose_fin(int lvl,
                                                   const float* __restrict__ b_comp) {
    int cnt = g_lvlcnt[lvl];
    if (cnt > MAXPERLVL) cnt = MAXPERLVL;
    int total = cnt << 10;
    for (int idx = blockIdx.x * 256 + threadIdx.x; idx < total; idx += gridDim.x * 256) {
        int op = idx >> 10, jh = idx & (NH - 1);
        const int* rec = g_list + ((size_t)lvl * MAXPERLVL + op) * 4;
        int dst = rec[0], cX = rec[1], cL = rec[2], cR = rec[3];
        float a[6];
#pragma unroll
        for (int g = 0; g < 6; g++) {
            int n = g * NH + jh;
            a[g] = b_comp[n]
                 + g_part[((size_t)0 * MAXPERLVL + op) * G6 + n]
                 + g_part[((size_t)1 * MAXPERLVL + op) * G6 + n]
                 + g_part[((size_t)2 * MAXPERLVL + op) * G6 + n];
        }
        float cl = 0.f, cx = 0.f, cr = 0.f;
        if (cL >= 0) cl = (cL < 4096) ? g_cs[(size_t)cL * NH + jh]
                                      : g_nc[(size_t)(cL - 4096) * NH + jh];
        if (cX >= 0) cx = (cX < 4096) ? g_cs[(size_t)cX * NH + jh]
                                      : g_nc[(size_t)(cX - 4096) * NH + jh];
        if (cR >= 0) cr = (cR < 4096) ? g_cs[(size_t)cR * NH + jh]
                                      : g_nc[(size_t)(cR - 4096) * NH + jh];
        float c = sigf(a[0]) * tanhf(a[4]) + sigf(a[1]) * cl
                + sigf(a[2]) * cx + sigf(a[3]) * cr;
        float h = sigf(a[5]) * tanhf(c);
        g_nh[(size_t)dst * NH + jh] = h;
        g_nc[(size_t)dst * NH + jh] = c;
    }
}

// -------------------- gather roots into output ------------------------------
__global__ void gather_out(float* __restrict__ out) {
    int idx = blockIdx.x * blockDim.x + threadIdx.x;  // 0..32767
    int b = idx >> 10, j = idx & (NH - 1);
    int code = g_root[b];
    float h = 0.f, c = 0.f;
    if (code >= 0) {
        if (code < 4096) {
            h = g_hs[(size_t)code * NH + j];
            c = g_cs[(size_t)code * NH + j];
        } else {
            int n = code - 4096;
            h = g_nh[(size_t)n * NH + j];
            c = g_nc[(size_t)n * NH + j];
        }
    }
    out[idx] = h;
    out[NB * NH + idx] = c;
}

// -------------------- launcher ---------------------------------------------
extern "C" void kernel_launch(void* const* d_in, const int* in_sizes, int n_in,
                              void* d_out, int out_size) {
    const float* x      = (const float*)d_in[0];  // (32,128,300)
    const float* W_ih   = (const float*)d_in[1];  // (4096,300)
    const float* W_hh   = (const float*)d_in[2];  // (4096,1024)
    const float* b_ih   = (const float*)d_in[3];  // (4096)
    const float* b_hh   = (const float*)d_in[4];  // (4096)
    const float* W_comp = (const float*)d_in[5];  // (6144,3072)
    const float* b_comp = (const float*)d_in[6];  // (6144)
    const int*   words  = (const int*)d_in[7];    // (32,128)
    const int*   lens   = (const int*)d_in[8];    // (32)
    float* out = (float*)d_out;

    void *pWtIh = 0, *pWtComp = 0;
    cudaGetSymbolAddress(&pWtIh, g_WtIh);
    cudaGetSymbolAddress(&pWtComp, g_WtComp);

    dim3 thr(32, 8);
    transposeK<<<dim3(128, 10), thr>>>(W_ih, (float*)pWtIh, G4, ND, KIH);
    transposeK<<<dim3(192, 96), thr>>>(W_comp, (float*)pWtComp, G6, K3, K3);
    transposeWhh<<<4096, 256>>>(W_hh);

    xg_gemm<<<dim3(32, 32), 256>>>(x, b_ih, b_hh);

    schedule<<<1, 32>>>(words, lens);
    listbuild<<<1, 32>>>();

    for (int t = 0; t < NL; t++)
        lstm_step<<<128, thr>>>(t);

    for (int lvl = 1; lvl < MAXLVL; lvl++) {
        compose_gemm<<<dim3(48, 48), 256>>>(lvl);
        compose_fin<<<256, 256>>>(lvl, b_comp);
    }

    gather_out<<<64, 512>>>(out);
}

// round 10
// speedup vs baseline: 1.8670x; 1.0829x over previous
#include <cuda_runtime.h>
#include <math.h>

#define NB 32
#define NL 128
#define ND 300
#define NH 1024
#define G4 4096
#define G6 6144
#define K3 3072
#define KIH 320          // D padded to multiple of 32
#define MAXLVL 48
#define MAXPERLVL 2048
#define NSPLIT 6         // split-K chunks (512 each) for compose

typedef unsigned long long u64;

// -------------------- f32x2 packed helpers (FFMA2 path) ---------------------
__device__ __forceinline__ u64 dup2(float x) {
    u64 r; asm("mov.b64 %0, {%1, %1};" : "=l"(r) : "f"(x)); return r;
}
__device__ __forceinline__ u64 pack2(float x, float y) {
    u64 r; asm("mov.b64 %0, {%1, %2};" : "=l"(r) : "f"(x), "f"(y)); return r;
}
__device__ __forceinline__ void ffma2(u64& d, u64 a, u64 b) {
    asm("fma.rn.f32x2 %0, %1, %2, %3;" : "=l"(d) : "l"(a), "l"(b), "l"(d));
}
__device__ __forceinline__ float2 unpk2(u64 v) {
    float2 f; asm("mov.b64 {%0, %1}, %2;" : "=f"(f.x), "=f"(f.y) : "l"(v)); return f;
}
__device__ __forceinline__ float sigf(float x) { return 1.f / (1.f + expf(-x)); }

// -------------------- scratch (device globals) ------------------------------
__device__ float g_WtIh[KIH * G4];
__device__ float g_WtHh[NH * G4];         // lstm interleaved layout
__device__ float g_WtComp[K3 * G6];
__device__ float g_Xg[(NB * NL) * G4];
__device__ float g_hs[NB * NL * NH];
__device__ float g_cs[NB * NL * NH];
__device__ float g_nh[NB * NL * NH];
__device__ float g_nc[NB * NL * NH];
__device__ float g_part[NSPLIT * MAXPERLVL * G6];
__device__ int   g_ops[NB * NL * 4];
__device__ int   g_nops[NB];
__device__ int   g_root[NB];
__device__ int   g_lvlcnt[MAXLVL];
__device__ int   g_list[MAXLVL * MAXPERLVL * 4]; // dst, xglob, lglob, rglob

// -------------------- transpose W[N][K] -> Wt[Kp][N] ------------------------
__global__ void transposeK(const float* __restrict__ W, float* __restrict__ Wt,
                           int N, int K, int Kp) {
    __shared__ float tile[32][33];
    int j0 = blockIdx.x * 32, k0 = blockIdx.y * 32;
    int tx = threadIdx.x, ty = threadIdx.y;
    for (int r = ty; r < 32; r += 8) {
        int j = j0 + r, k = k0 + tx;
        tile[r][tx] = (j < N && k < K) ? W[(size_t)j * K + k] : 0.f;
    }
    __syncthreads();
    for (int r = ty; r < 32; r += 8) {
        int k = k0 + r, j = j0 + tx;
        if (k < Kp && j < N) Wt[(size_t)k * N + j] = tile[tx][r];
    }
}

// -------------------- W_hh -> k-major interleaved for lstm ------------------
__global__ void transposeWhh(const float* __restrict__ W) {
    int row = blockIdx.x;                    // gate*1024 + jh
    int gate = row >> 10, jh = row & 1023;
    int colp = ((jh >> 3) << 5) + ((jh & 7) << 2) + gate;
    const float* src = W + (size_t)row * NH;
    for (int k = threadIdx.x; k < NH; k += 256)
        g_WtHh[(size_t)k * G4 + colp] = src[k];
}

// -------------------- Xg = x @ WtIh + b_ih + b_hh (f32x2 sgemm) -------------
__global__ __launch_bounds__(256) void xg_gemm(const float* __restrict__ x,
                                               const float* __restrict__ b_ih,
                                               const float* __restrict__ b_hh) {
    __shared__ float As[16][132];
    __shared__ float Bs[16][128];
    int tid = threadIdx.x;
    int tx = tid & 15, ty = tid >> 4;
    int n0 = blockIdx.x * 128, m0 = blockIdx.y * 128;
    u64 acc[8][4];
#pragma unroll
    for (int i = 0; i < 8; i++)
#pragma unroll
        for (int q = 0; q < 4; q++) acc[i][q] = 0ull;

    for (int k0 = 0; k0 < KIH; k0 += 16) {
        __syncthreads();
        {
            int r = tid >> 1;
            int kb = (tid & 1) * 8;
            const float* xr = x + (size_t)(m0 + r) * ND + k0 + kb;
#pragma unroll
            for (int i = 0; i < 8; i++) {
                int k = k0 + kb + i;
                As[kb + i][r] = (k < ND) ? xr[i] : 0.f;
            }
            int br = tid >> 4, bc = (tid & 15) * 8;
            const float* wb = g_WtIh + (size_t)(k0 + br) * G4 + n0 + bc;
            *(float4*)&Bs[br][bc]     = *(const float4*)(wb);
            *(float4*)&Bs[br][bc + 4] = *(const float4*)(wb + 4);
        }
        __syncthreads();
#pragma unroll
        for (int kk = 0; kk < 16; kk++) {
            float4 a0 = *(const float4*)&As[kk][ty * 4];
            float4 a1 = *(const float4*)&As[kk][64 + ty * 4];
            u64 ad[8] = {dup2(a0.x), dup2(a0.y), dup2(a0.z), dup2(a0.w),
                         dup2(a1.x), dup2(a1.y), dup2(a1.z), dup2(a1.w)};
            ulonglong2 bb0 = *(const ulonglong2*)&Bs[kk][tx * 4];
            ulonglong2 bb1 = *(const ulonglong2*)&Bs[kk][64 + tx * 4];
#pragma unroll
            for (int i = 0; i < 8; i++) {
                ffma2(acc[i][0], ad[i], bb0.x);
                ffma2(acc[i][1], ad[i], bb0.y);
                ffma2(acc[i][2], ad[i], bb1.x);
                ffma2(acc[i][3], ad[i], bb1.y);
            }
        }
    }
#pragma unroll
    for (int hm = 0; hm < 2; hm++)
#pragma unroll
        for (int i = 0; i < 4; i++) {
            int m = m0 + hm * 64 + ty * 4 + i;
            float* orow = g_Xg + (size_t)m * G4 + n0;
#pragma unroll
            for (int hn = 0; hn < 2; hn++) {
                int nb = hn * 64 + tx * 4;
                float2 p0 = unpk2(acc[hm * 4 + i][hn * 2 + 0]);
                float2 p1 = unpk2(acc[hm * 4 + i][hn * 2 + 1]);
                float4 v;
                v.x = p0.x + b_ih[n0 + nb + 0] + b_hh[n0 + nb + 0];
                v.y = p0.y + b_ih[n0 + nb + 1] + b_hh[n0 + nb + 1];
                v.z = p1.x + b_ih[n0 + nb + 2] + b_hh[n0 + nb + 2];
                v.w = p1.y + b_ih[n0 + nb + 3] + b_hh[n0 + nb + 3];
                *(float4*)&orow[nb] = v;
            }
        }
}

// -------------------- one recurrent LSTM step (f32x2) -----------------------
__global__ __launch_bounds__(256) void lstm_step(int t) {
    __shared__ float Hs[32][33];
    __shared__ float Ws[32][32];     // [kk][jl*4 + gate]
    int tx = threadIdx.x, ty = threadIdx.y;
    int j0 = blockIdx.x * 8;
    int b = tx, jh = j0 + ty;
    size_t xbase = (size_t)(b * NL + t) * G4 + jh;
    u64 A01 = pack2(g_Xg[xbase + 0 * NH], g_Xg[xbase + 1 * NH]);
    u64 A23 = pack2(g_Xg[xbase + 2 * NH], g_Xg[xbase + 3 * NH]);
    if (t > 0) {
        int cb = blockIdx.x << 5;
        for (int k0 = 0; k0 < NH; k0 += 32) {
#pragma unroll
            for (int p = 0; p < 4; p++) {
                int r = ty + p * 8;
                Hs[r][tx] = g_hs[(size_t)(r * NL + (t - 1)) * NH + k0 + tx];
                Ws[r][tx] = g_WtHh[(size_t)(k0 + r) * G4 + cb + tx];
            }
            __syncthreads();
#pragma unroll
            for (int kk = 0; kk < 32; kk++) {
                u64 hd = dup2(Hs[tx][kk]);
                ulonglong2 w = *(const ulonglong2*)&Ws[kk][ty * 4];
                ffma2(A01, hd, w.x);
                ffma2(A23, hd, w.y);
            }
            __syncthreads();
        }
    }
    float2 gif = unpk2(A01);   // (i, f)
    float2 ggo = unpk2(A23);   // (g, o)
    float cprev = (t > 0) ? g_cs[(size_t)(b * NL + (t - 1)) * NH + jh] : 0.f;
    float c = sigf(gif.y) * cprev + sigf(gif.x) * tanhf(ggo.x);
    float h = sigf(ggo.y) * tanhf(c);
    g_hs[(size_t)(b * NL + t) * NH + jh] = h;
    g_cs[(size_t)(b * NL + t) * NH + jh] = c;
}

// -------------------- tree schedule: per-batch greedy build -----------------
__global__ void schedule(const int* __restrict__ words, const int* __restrict__ lens) {
    int b = threadIdx.x;
    for (int i = b; i < MAXLVL; i += 32) g_lvlcnt[i] = 0;
    if (b >= NB) return;
    int len = lens[b];
    if (len > NL) len = NL;
    if (len < 0) len = 0;
    int keys[NL];
    for (int l = 0; l < len; l++) keys[l] = words[b * NL + l] % 1000;
    int oplv[NL];
    int st_s[NL + 4], st_e[NL + 4], st_p[NL + 4], st_st[NL + 4], st_l[NL + 4];
    int sp = 0;
    st_s[0] = 0; st_e[0] = len; st_st[0] = 0; sp = 1;
    int ret = -1, nops = 0;
    while (sp > 0) {
        int i = sp - 1;
        int stage = st_st[i];
        if (stage == 0) {
            int s = st_s[i], e = st_e[i];
            if (e <= s)            { ret = -1; sp--; }
            else if (e == s + 1)   { ret = s;  sp--; }
            else {
                int bk = 0x7fffffff, bp = s;
                for (int l = s; l < e; l++)
                    if (keys[l] < bk) { bk = keys[l]; bp = l; }
                st_p[i] = bp; st_st[i] = 1;
                st_s[sp] = s; st_e[sp] = bp; st_st[sp] = 0; sp++;
            }
        } else if (stage == 1) {
            st_l[i] = ret; st_st[i] = 2;
            st_s[sp] = st_p[i] + 1; st_e[sp] = st_e[i]; st_st[sp] = 0; sp++;
        } else {
            int li = st_l[i], ri = ret;
            int ll = (li >= 1000) ? oplv[li - 1000] : 0;
            int rl = (ri >= 1000) ? oplv[ri - 1000] : 0;
            int lvl = 1 + (ll > rl ? ll : rl);
            int idx = nops++;
            oplv[idx] = lvl;
            int base = (b * NL + idx) * 4;
            g_ops[base + 0] = st_p[i];
            g_ops[base + 1] = li;
            g_ops[base + 2] = ri;
            g_ops[base + 3] = lvl;
            ret = 1000 + idx; sp--;
        }
    }
    g_nops[b] = nops;
    int root;
    if (ret >= 1000)      root = 4096 + b * NL + (ret - 1000);
    else if (ret >= 0)    root = b * NL + ret;
    else                  root = -1;
    g_root[b] = root;
}

// -------------------- bucket ops into per-level work lists ------------------
__global__ void listbuild() {
    int b = threadIdx.x;
    if (b >= NB) return;
    int n = g_nops[b];
    for (int i = 0; i < n; i++) {
        int base = (b * NL + i) * 4;
        int xp  = g_ops[base + 0];
        int li  = g_ops[base + 1];
        int ri  = g_ops[base + 2];
        int lvl = g_ops[base + 3];
        if (lvl >= MAXLVL) lvl = MAXLVL - 1;
        int slot = atomicAdd(&g_lvlcnt[lvl], 1);
        if (slot < MAXPERLVL) {
            int lb = (lvl * MAXPERLVL + slot) * 4;
            g_list[lb + 0] = b * NL + i;
            g_list[lb + 1] = b * NL + xp;
            g_list[lb + 2] = (li < 0) ? -1 : (li < 1000 ? b * NL + li
                                                        : 4096 + b * NL + (li - 1000));
            g_list[lb + 3] = (ri < 0) ? -1 : (ri < 1000 ? b * NL + ri
                                                        : 4096 + b * NL + (ri - 1000));
        }
    }
}

// -------------------- compose GEMM: one level, 6-way split-K, f32x2 ---------
// grid (96, 24): bx -> (ksp = bx%6, mg = bx/6), by -> 256-wide n-tile.
// ksp: child seg = ksp>>1 (0=l,1=x,2=r), K-half = (ksp&1)*512. K per block = 512.
// Block tile 32(M) x 256(N); 256 threads; thread = 4M x 8N (16 packed acc).
__global__ __launch_bounds__(256, 2) void compose_gemm(int lvl) {
    int cnt = g_lvlcnt[lvl];
    if (cnt > MAXPERLVL) cnt = MAXPERLVL;
    if (cnt == 0) return;
    int ksp = blockIdx.x % 6, mg = blockIdx.x / 6;
    int seg = ksp >> 1;
    int kb0 = seg * NH + (ksp & 1) * 512;      // row offset into WtComp/K
    int n0 = blockIdx.y * 256;
    __shared__ float As[32][36];               // [kk][m], 16B-aligned rows
    __shared__ float Bs[32][256];
    __shared__ int s_ch[32];
    int tid = threadIdx.x;
    int tx = tid & 31, ty = tid >> 5;          // tx: n-group, ty: m-group (warp-uniform)
    int arow = tid >> 3, ak4 = (tid & 7) * 4;  // A-gather mapping
    int nmt = (cnt + 31) >> 5;

    for (int mb = mg; mb < nmt; mb += 16) {
        __syncthreads();
        if (tid < 32) {
            int op = mb * 32 + tid;
            if (op > cnt - 1) op = cnt - 1;
            const int* rec = g_list + ((size_t)lvl * MAXPERLVL + op) * 4;
            s_ch[tid] = (seg == 0) ? rec[2] : ((seg == 1) ? rec[1] : rec[3]);
        }
        __syncthreads();
        int code = s_ch[arow];
        const float* hp = 0;
        if (code >= 0)
            hp = (code < 4096) ? (g_hs + (size_t)code * NH)
                               : (g_nh + (size_t)(code - 4096) * NH);
        u64 acc[4][4];
#pragma unroll
        for (int i = 0; i < 4; i++)
#pragma unroll
            for (int q = 0; q < 4; q++) acc[i][q] = 0ull;

        for (int kt = 0; kt < 16; kt++) {
            int kb = kt * 32;
            float4 av = make_float4(0.f, 0.f, 0.f, 0.f);
            if (code >= 0)
                av = *(const float4*)(hp + (ksp & 1) * 512 + kb + ak4);
            __syncthreads();
            As[ak4 + 0][arow] = av.x;
            As[ak4 + 1][arow] = av.y;
            As[ak4 + 2][arow] = av.z;
            As[ak4 + 3][arow] = av.w;
            {   // Bs: 32 rows x 256 cols; 8 float4 per thread, coalesced
#pragma unroll
                for (int i = 0; i < 8; i++) {
                    int f4 = i * 256 + tid;
                    int row = f4 >> 6, c4 = (f4 & 63) << 2;
                    *(float4*)&Bs[row][c4] =
                        *(const float4*)(g_WtComp + (size_t)(kb0 + kb + row) * G6 + n0 + c4);
                }
            }
            __syncthreads();
#pragma unroll
            for (int kk = 0; kk < 32; kk++) {
                float4 a = *(const float4*)&As[kk][ty * 4];
                u64 d0 = dup2(a.x), d1 = dup2(a.y), d2 = dup2(a.z), d3 = dup2(a.w);
                ulonglong2 b0 = *(const ulonglong2*)&Bs[kk][tx * 8];
                ulonglong2 b1 = *(const ulonglong2*)&Bs[kk][tx * 8 + 4];
                ffma2(acc[0][0], d0, b0.x); ffma2(acc[0][1], d0, b0.y);
                ffma2(acc[0][2], d0, b1.x); ffma2(acc[0][3], d0, b1.y);
                ffma2(acc[1][0], d1, b0.x); ffma2(acc[1][1], d1, b0.y);
                ffma2(acc[1][2], d1, b1.x); ffma2(acc[1][3], d1, b1.y);
                ffma2(acc[2][0], d2, b0.x); ffma2(acc[2][1], d2, b0.y);
                ffma2(acc[2][2], d2, b1.x); ffma2(acc[2][3], d2, b1.y);
                ffma2(acc[3][0], d3, b0.x); ffma2(acc[3][1], d3, b0.y);
                ffma2(acc[3][2], d3, b1.x); ffma2(acc[3][3], d3, b1.y);
            }
        }
#pragma unroll
        for (int i = 0; i < 4; i++) {
            int op = mb * 32 + ty * 4 + i;
            if (op < cnt) {
                float* pp = g_part + ((size_t)ksp * MAXPERLVL + op) * G6 + n0;
                ulonglong2 v0; v0.x = acc[i][0]; v0.y = acc[i][1];
                ulonglong2 v1; v1.x = acc[i][2]; v1.y = acc[i][3];
                *(ulonglong2*)&pp[tx * 8]     = v0;
                *(ulonglong2*)&pp[tx * 8 + 4] = v1;
            }
        }
    }
}

// -------------------- compose finalize: sum 6 partials + cell ---------------
__global__ __launch_bounds__(256) void compose_fin(int lvl,
                                                   const float* __restrict__ b_comp) {
    int cnt = g_lvlcnt[lvl];
    if (cnt > MAXPERLVL) cnt = MAXPERLVL;
    int total = cnt << 10;
    for (int idx = blockIdx.x * 256 + threadIdx.x; idx < total; idx += gridDim.x * 256) {
        int op = idx >> 10, jh = idx & (NH - 1);
        const int* rec = g_list + ((size_t)lvl * MAXPERLVL + op) * 4;
        int dst = rec[0], cX = rec[1], cL = rec[2], cR = rec[3];
        float a[6];
#pragma unroll
        for (int g = 0; g < 6; g++) {
            int n = g * NH + jh;
            float s = b_comp[n];
#pragma unroll
            for (int p = 0; p < NSPLIT; p++)
                s += g_part[((size_t)p * MAXPERLVL + op) * G6 + n];
            a[g] = s;
        }
        float cl = 0.f, cx = 0.f, cr = 0.f;
        if (cL >= 0) cl = (cL < 4096) ? g_cs[(size_t)cL * NH + jh]
                                      : g_nc[(size_t)(cL - 4096) * NH + jh];
        if (cX >= 0) cx = (cX < 4096) ? g_cs[(size_t)cX * NH + jh]
                                      : g_nc[(size_t)(cX - 4096) * NH + jh];
        if (cR >= 0) cr = (cR < 4096) ? g_cs[(size_t)cR * NH + jh]
                                      : g_nc[(size_t)(cR - 4096) * NH + jh];
        float c = sigf(a[0]) * tanhf(a[4]) + sigf(a[1]) * cl
                + sigf(a[2]) * cx + sigf(a[3]) * cr;
        float h = sigf(a[5]) * tanhf(c);
        g_nh[(size_t)dst * NH + jh] = h;
        g_nc[(size_t)dst * NH + jh] = c;
    }
}

// -------------------- gather roots into output ------------------------------
__global__ void gather_out(float* __restrict__ out) {
    int idx = blockIdx.x * blockDim.x + threadIdx.x;  // 0..32767
    int b = idx >> 10, j = idx & (NH - 1);
    int code = g_root[b];
    float h = 0.f, c = 0.f;
    if (code >= 0) {
        if (code < 4096) {
            h = g_hs[(size_t)code * NH + j];
            c = g_cs[(size_t)code * NH + j];
        } else {
            int n = code - 4096;
            h = g_nh[(size_t)n * NH + j];
            c = g_nc[(size_t)n * NH + j];
        }
    }
    out[idx] = h;
    out[NB * NH + idx] = c;
}

// -------------------- launcher ---------------------------------------------
extern "C" void kernel_launch(void* const* d_in, const int* in_sizes, int n_in,
                              void* d_out, int out_size) {
    const float* x      = (const float*)d_in[0];
    const float* W_ih   = (const float*)d_in[1];
    const float* W_hh   = (const float*)d_in[2];
    const float* b_ih   = (const float*)d_in[3];
    const float* b_hh   = (const float*)d_in[4];
    const float* W_comp = (const float*)d_in[5];
    const float* b_comp = (const float*)d_in[6];
    const int*   words  = (const int*)d_in[7];
    const int*   lens   = (const int*)d_in[8];
    float* out = (float*)d_out;

    void *pWtIh = 0, *pWtComp = 0;
    cudaGetSymbolAddress(&pWtIh, g_WtIh);
    cudaGetSymbolAddress(&pWtComp, g_WtComp);

    dim3 thr(32, 8);
    transposeK<<<dim3(128, 10), thr>>>(W_ih, (float*)pWtIh, G4, ND, KIH);
    transposeK<<<dim3(192, 96), thr>>>(W_comp, (float*)pWtComp, G6, K3, K3);
    transposeWhh<<<4096, 256>>>(W_hh);

    xg_gemm<<<dim3(32, 32), 256>>>(x, b_ih, b_hh);

    schedule<<<1, 32>>>(words, lens);
    listbuild<<<1, 32>>>();

    for (int t = 0; t < NL; t++)
        lstm_step<<<128, thr>>>(t);

    for (int lvl = 1; lvl < MAXLVL; lvl++) {
        compose_gemm<<<dim3(96, 24), 256>>>(lvl);
        compose_fin<<<256, 256>>>(lvl, b_comp);
    }

    gather_out<<<64, 512>>>(out);
}

// round 12
// speedup vs baseline: 2.6446x; 1.4165x over previous
#include <cuda_runtime.h>
#include <cuda_bf16.h>
#include <math.h>
#include <stdint.h>

#define NB 32
#define NL 128
#define ND 300
#define NH 1024
#define G4 4096
#define G6 6144
#define K3 3072
#define KIH 320
#define MAXLVL 48
#define MAXPERLVL 2048
#define NSPLIT 6

typedef unsigned long long u64;

// -------------------- f32x2 packed helpers (FFMA2 path) ---------------------
__device__ __forceinline__ u64 dup2(float x) {
    u64 r; asm("mov.b64 %0, {%1, %1};" : "=l"(r) : "f"(x)); return r;
}
__device__ __forceinline__ u64 pack2(float x, float y) {
    u64 r; asm("mov.b64 %0, {%1, %2};" : "=l"(r) : "f"(x), "f"(y)); return r;
}
__device__ __forceinline__ void ffma2(u64& d, u64 a, u64 b) {
    asm("fma.rn.f32x2 %0, %1, %2, %3;" : "=l"(d) : "l"(a), "l"(b), "l"(d));
}
__device__ __forceinline__ float2 unpk2(u64 v) {
    float2 f; asm("mov.b64 {%0, %1}, %2;" : "=f"(f.x), "=f"(f.y) : "l"(v)); return f;
}
__device__ __forceinline__ float sigf(float x) { return 1.f / (1.f + expf(-x)); }

// -------------------- legacy tensor-core helpers (compute_103-safe) ---------
__device__ __forceinline__ uint32_t smem_u32(const void* p) {
    return (uint32_t)__cvta_generic_to_shared(p);
}
__device__ __forceinline__ void ldm_x4(uint32_t* r, uint32_t addr) {
    asm volatile("ldmatrix.sync.aligned.m8n8.x4.shared.b16 {%0,%1,%2,%3}, [%4];"
        : "=r"(r[0]), "=r"(r[1]), "=r"(r[2]), "=r"(r[3]) : "r"(addr));
}
__device__ __forceinline__ void mma_bf16(float* c, const uint32_t* a, const uint32_t* b) {
    asm volatile("mma.sync.aligned.m16n8k16.row.col.f32.bf16.bf16.f32 "
        "{%0,%1,%2,%3}, {%4,%5,%6,%7}, {%8,%9}, {%0,%1,%2,%3};"
        : "+f"(c[0]), "+f"(c[1]), "+f"(c[2]), "+f"(c[3])
        : "r"(a[0]), "r"(a[1]), "r"(a[2]), "r"(a[3]), "r"(b[0]), "r"(b[1]));
}
#define SWZ(b) ((b) ^ (((b) >> 3) & 0x70))

// -------------------- scratch (device globals) ------------------------------
__device__ float g_WtIh[KIH * G4];
__device__ float g_WtHh[NH * G4];
__device__ __nv_bfloat16 g_Wc_hi[(size_t)G6 * K3];   // [n][k]
__device__ __nv_bfloat16 g_Wc_lo[(size_t)G6 * K3];
__device__ float g_Xg[(NB * NL) * G4];
__device__ float g_hs[NB * NL * NH];
__device__ float g_cs[NB * NL * NH];
__device__ float g_nh[NB * NL * NH];
__device__ float g_nc[NB * NL * NH];
__device__ float g_part[(size_t)NSPLIT * MAXPERLVL * G6];
__device__ int   g_ops[NB * NL * 4];
__device__ int   g_nops[NB];
__device__ int   g_root[NB];
__device__ int   g_lvlcnt[MAXLVL];
__device__ int   g_list[MAXLVL * MAXPERLVL * 4];

// -------------------- transpose W[N][K] -> Wt[Kp][N] ------------------------
__global__ void transposeK(const float* __restrict__ W, float* __restrict__ Wt,
                           int N, int K, int Kp) {
    __shared__ float tile[32][33];
    int j0 = blockIdx.x * 32, k0 = blockIdx.y * 32;
    int tx = threadIdx.x, ty = threadIdx.y;
    for (int r = ty; r < 32; r += 8) {
        int j = j0 + r, k = k0 + tx;
        tile[r][tx] = (j < N && k < K) ? W[(size_t)j * K + k] : 0.f;
    }
    __syncthreads();
    for (int r = ty; r < 32; r += 8) {
        int k = k0 + r, j = j0 + tx;
        if (k < Kp && j < N) Wt[(size_t)k * N + j] = tile[tx][r];
    }
}

// -------------------- W_hh -> k-major interleaved for lstm ------------------
__global__ void transposeWhh(const float* __restrict__ W) {
    int row = blockIdx.x;
    int gate = row >> 10, jh = row & 1023;
    int colp = ((jh >> 3) << 5) + ((jh & 7) << 2) + gate;
    const float* src = W + (size_t)row * NH;
    for (int k = threadIdx.x; k < NH; k += 256)
        g_WtHh[(size_t)k * G4 + colp] = src[k];
}

// -------------------- split W_comp into bf16 hi/lo (native [n][k]) ----------
__global__ void packWcomp(const float* __restrict__ W) {
    size_t i = (size_t)blockIdx.x * 256 + threadIdx.x;
    if (i < (size_t)G6 * K3) {
        float v = W[i];
        __nv_bfloat16 h = __float2bfloat16(v);
        g_Wc_hi[i] = h;
        g_Wc_lo[i] = __float2bfloat16(v - __bfloat162float(h));
    }
}

// -------------------- Xg = x @ WtIh + b_ih + b_hh (f32x2 sgemm) -------------
__global__ __launch_bounds__(256) void xg_gemm(const float* __restrict__ x,
                                               const float* __restrict__ b_ih,
                                               const float* __restrict__ b_hh) {
    __shared__ float As[16][132];
    __shared__ float Bs[16][128];
    int tid = threadIdx.x;
    int tx = tid & 15, ty = tid >> 4;
    int n0 = blockIdx.x * 128, m0 = blockIdx.y * 128;
    u64 acc[8][4];
#pragma unroll
    for (int i = 0; i < 8; i++)
#pragma unroll
        for (int q = 0; q < 4; q++) acc[i][q] = 0ull;

    for (int k0 = 0; k0 < KIH; k0 += 16) {
        __syncthreads();
        {
            int r = tid >> 1;
            int kb = (tid & 1) * 8;
            const float* xr = x + (size_t)(m0 + r) * ND + k0 + kb;
#pragma unroll
            for (int i = 0; i < 8; i++) {
                int k = k0 + kb + i;
                As[kb + i][r] = (k < ND) ? xr[i] : 0.f;
            }
            int br = tid >> 4, bc = (tid & 15) * 8;
            const float* wb = g_WtIh + (size_t)(k0 + br) * G4 + n0 + bc;
            *(float4*)&Bs[br][bc]     = *(const float4*)(wb);
            *(float4*)&Bs[br][bc + 4] = *(const float4*)(wb + 4);
        }
        __syncthreads();
#pragma unroll
        for (int kk = 0; kk < 16; kk++) {
            float4 a0 = *(const float4*)&As[kk][ty * 4];
            float4 a1 = *(const float4*)&As[kk][64 + ty * 4];
            u64 ad[8] = {dup2(a0.x), dup2(a0.y), dup2(a0.z), dup2(a0.w),
                         dup2(a1.x), dup2(a1.y), dup2(a1.z), dup2(a1.w)};
            ulonglong2 bb0 = *(const ulonglong2*)&Bs[kk][tx * 4];
            ulonglong2 bb1 = *(const ulonglong2*)&Bs[kk][64 + tx * 4];
#pragma unroll
            for (int i = 0; i < 8; i++) {
                ffma2(acc[i][0], ad[i], bb0.x);
                ffma2(acc[i][1], ad[i], bb0.y);
                ffma2(acc[i][2], ad[i], bb1.x);
                ffma2(acc[i][3], ad[i], bb1.y);
            }
        }
    }
#pragma unroll
    for (int hm = 0; hm < 2; hm++)
#pragma unroll
        for (int i = 0; i < 4; i++) {
            int m = m0 + hm * 64 + ty * 4 + i;
            float* orow = g_Xg + (size_t)m * G4 + n0;
#pragma unroll
            for (int hn = 0; hn < 2; hn++) {
                int nb = hn * 64 + tx * 4;
                float2 p0 = unpk2(acc[hm * 4 + i][hn * 2 + 0]);
                float2 p1 = unpk2(acc[hm * 4 + i][hn * 2 + 1]);
                float4 v;
                v.x = p0.x + b_ih[n0 + nb + 0] + b_hh[n0 + nb + 0];
                v.y = p0.y + b_ih[n0 + nb + 1] + b_hh[n0 + nb + 1];
                v.z = p1.x + b_ih[n0 + nb + 2] + b_hh[n0 + nb + 2];
                v.w = p1.y + b_ih[n0 + nb + 3] + b_hh[n0 + nb + 3];
                *(float4*)&orow[nb] = v;
            }
        }
}

// -------------------- one recurrent LSTM step (f32x2) -----------------------
__global__ __launch_bounds__(256) void lstm_step(int t) {
    __shared__ float Hs[32][33];
    __shared__ float Ws[32][32];
    int tx = threadIdx.x, ty = threadIdx.y;
    int j0 = blockIdx.x * 8;
    int b = tx, jh = j0 + ty;
    size_t xbase = (size_t)(b * NL + t) * G4 + jh;
    u64 A01 = pack2(g_Xg[xbase + 0 * NH], g_Xg[xbase + 1 * NH]);
    u64 A23 = pack2(g_Xg[xbase + 2 * NH], g_Xg[xbase + 3 * NH]);
    if (t > 0) {
        int cb = blockIdx.x << 5;
        for (int k0 = 0; k0 < NH; k0 += 32) {
#pragma unroll
            for (int p = 0; p < 4; p++) {
                int r = ty + p * 8;
                Hs[r][tx] = g_hs[(size_t)(r * NL + (t - 1)) * NH + k0 + tx];
                Ws[r][tx] = g_WtHh[(size_t)(k0 + r) * G4 + cb + tx];
            }
            __syncthreads();
#pragma unroll
            for (int kk = 0; kk < 32; kk++) {
                u64 hd = dup2(Hs[tx][kk]);
                ulonglong2 w = *(const ulonglong2*)&Ws[kk][ty * 4];
                ffma2(A01, hd, w.x);
                ffma2(A23, hd, w.y);
            }
            __syncthreads();
        }
    }
    float2 gif = unpk2(A01);
    float2 ggo = unpk2(A23);
    float cprev = (t > 0) ? g_cs[(size_t)(b * NL + (t - 1)) * NH + jh] : 0.f;
    float c = sigf(gif.y) * cprev + sigf(gif.x) * tanhf(ggo.x);
    float h = sigf(ggo.y) * tanhf(c);
    g_hs[(size_t)(b * NL + t) * NH + jh] = h;
    g_cs[(size_t)(b * NL + t) * NH + jh] = c;
}

// -------------------- tree schedule: per-batch greedy build -----------------
__global__ void schedule(const int* __restrict__ words, const int* __restrict__ lens) {
    int b = threadIdx.x;
    for (int i = b; i < MAXLVL; i += 32) g_lvlcnt[i] = 0;
    if (b >= NB) return;
    int len = lens[b];
    if (len > NL) len = NL;
    if (len < 0) len = 0;
    int keys[NL];
    for (int l = 0; l < len; l++) keys[l] = words[b * NL + l] % 1000;
    int oplv[NL];
    int st_s[NL + 4], st_e[NL + 4], st_p[NL + 4], st_st[NL + 4], st_l[NL + 4];
    int sp = 0;
    st_s[0] = 0; st_e[0] = len; st_st[0] = 0; sp = 1;
    int ret = -1, nops = 0;
    while (sp > 0) {
        int i = sp - 1;
        int stage = st_st[i];
        if (stage == 0) {
            int s = st_s[i], e = st_e[i];
            if (e <= s)            { ret = -1; sp--; }
            else if (e == s + 1)   { ret = s;  sp--; }
            else {
                int bk = 0x7fffffff, bp = s;
                for (int l = s; l < e; l++)
                    if (keys[l] < bk) { bk = keys[l]; bp = l; }
                st_p[i] = bp; st_st[i] = 1;
                st_s[sp] = s; st_e[sp] = bp; st_st[sp] = 0; sp++;
            }
        } else if (stage == 1) {
            st_l[i] = ret; st_st[i] = 2;
            st_s[sp] = st_p[i] + 1; st_e[sp] = st_e[i]; st_st[sp] = 0; sp++;
        } else {
            int li = st_l[i], ri = ret;
            int ll = (li >= 1000) ? oplv[li - 1000] : 0;
            int rl = (ri >= 1000) ? oplv[ri - 1000] : 0;
            int lvl = 1 + (ll > rl ? ll : rl);
            int idx = nops++;
            oplv[idx] = lvl;
            int base = (b * NL + idx) * 4;
            g_ops[base + 0] = st_p[i];
            g_ops[base + 1] = li;
            g_ops[base + 2] = ri;
            g_ops[base + 3] = lvl;
            ret = 1000 + idx; sp--;
        }
    }
    g_nops[b] = nops;
    int root;
    if (ret >= 1000)      root = 4096 + b * NL + (ret - 1000);
    else if (ret >= 0)    root = b * NL + ret;
    else                  root = -1;
    g_root[b] = root;
}

// -------------------- bucket ops into per-level work lists ------------------
__global__ void listbuild() {
    int b = threadIdx.x;
    if (b >= NB) return;
    int n = g_nops[b];
    for (int i = 0; i < n; i++) {
        int base = (b * NL + i) * 4;
        int xp  = g_ops[base + 0];
        int li  = g_ops[base + 1];
        int ri  = g_ops[base + 2];
        int lvl = g_ops[base + 3];
        if (lvl >= MAXLVL) lvl = MAXLVL - 1;
        int slot = atomicAdd(&g_lvlcnt[lvl], 1);
        if (slot < MAXPERLVL) {
            int lb = (lvl * MAXPERLVL + slot) * 4;
            g_list[lb + 0] = b * NL + i;
            g_list[lb + 1] = b * NL + xp;
            g_list[lb + 2] = (li < 0) ? -1 : (li < 1000 ? b * NL + li
                                                        : 4096 + b * NL + (li - 1000));
            g_list[lb + 3] = (ri < 0) ? -1 : (ri < 1000 ? b * NL + ri
                                                        : 4096 + b * NL + (ri - 1000));
        }
    }
}

// -------------------- compose via mma.sync bf16 3-pass split ----------------
// grid (288, 16): bx -> (ksp = bx%6, ntile = bx/6); by = m-slot (stride 16).
// ksp: seg = ksp>>1 (l/x/r child), khalf = ksp&1 (K 512-half). Block tile:
// M=64 ops x N=128 x K=512 (8 chunks of 64). 8 warps = 2(M) x 4(N), warp 32x32.
// C += Ahi*Bhi + Alo*Bhi + Ahi*Blo, fp32 accum -> g_part[ksp].
#define SA_HI 0
#define SA_LO 8192
#define SB_HI 16384
#define SB_LO 32768
#define SM_CH 49152
#define CSMEM 49408

__global__ void __launch_bounds__(256) compose_mma(int lvl) {
    int cnt = g_lvlcnt[lvl];
    if (cnt > MAXPERLVL) cnt = MAXPERLVL;
    if (cnt == 0) return;
    int mtiles = (cnt + 63) >> 6;
    if ((int)blockIdx.y >= mtiles) return;
    int ksp = blockIdx.x % 6;
    int n0 = (blockIdx.x / 6) * 128;
    int seg = ksp >> 1, khalf = ksp & 1;
    int hoff = khalf * 512;                 // h-vector k offset
    int wk0 = seg * NH + khalf * 512;       // W_comp column base

    extern __shared__ char smem[];
    uint32_t sb = smem_u32(smem);
    int* s_ch = (int*)(smem + SM_CH);
    int tid = threadIdx.x;
    int lane = tid & 31, wid = tid >> 5;
    int mbase = (wid >> 2) * 32;            // warp m offset (0/32)
    int nbase = (wid & 3) * 32;             // warp n offset (0/32/64/96)

    // ldmatrix lane addressing pieces
    int a_row = (lane & 7) + ((lane >> 3) & 1) * 8;       // + m16 base
    int a_kb  = (lane >> 4) * 16;                          // + ks*32
    int b_row = (lane & 7) + ((lane >> 4) & 1) * 8;       // + n16 base
    int b_kb  = ((lane >> 3) & 1) * 16;                    // + ks*32

    for (int mb = blockIdx.y; mb < mtiles; mb += 16) {
        __syncthreads();
        if (tid < 64) {
            int op = mb * 64 + tid;
            if (op > cnt - 1) op = cnt - 1;
            const int* rec = g_list + ((size_t)lvl * MAXPERLVL + op) * 4;
            s_ch[tid] = (seg == 0) ? rec[2] : ((seg == 1) ? rec[1] : rec[3]);
        }
        __syncthreads();

        float acc[2][4][4];
#pragma unroll
        for (int i = 0; i < 2; i++)
#pragma unroll
            for (int j = 0; j < 4; j++)
#pragma unroll
                for (int q = 0; q < 4; q++) acc[i][j][q] = 0.f;

        for (int ch = 0; ch < 8; ch++) {
            int kc = ch * 64;
            __syncthreads();
            // ---- A gather + bf16 split: 64 rows x 64 k ----
            {
                int r = tid >> 2, kq = (tid & 3) * 16;
                int code = s_ch[r];
                const float* hp = 0;
                if (code >= 0)
                    hp = (code < 4096) ? (g_hs + (size_t)code * NH)
                                       : (g_nh + (size_t)(code - 4096) * NH);
#pragma unroll
                for (int j = 0; j < 16; j += 4) {
                    float4 v = (code >= 0)
                        ? *(const float4*)(hp + hoff + kc + kq + j)
                        : make_float4(0.f, 0.f, 0.f, 0.f);
                    __nv_bfloat16 hx = __float2bfloat16(v.x);
                    __nv_bfloat16 hy = __float2bfloat16(v.y);
                    __nv_bfloat16 hz = __float2bfloat16(v.z);
                    __nv_bfloat16 hw = __float2bfloat16(v.w);
                    __nv_bfloat162 hi01, hi23, lo01, lo23;
                    hi01.x = hx; hi01.y = hy; hi23.x = hz; hi23.y = hw;
                    lo01.x = __float2bfloat16(v.x - __bfloat162float(hx));
                    lo01.y = __float2bfloat16(v.y - __bfloat162float(hy));
                    lo23.x = __float2bfloat16(v.z - __bfloat162float(hz));
                    lo23.y = __float2bfloat16(v.w - __bfloat162float(hw));
                    uint32_t sw = SWZ((uint32_t)(r * 128 + (kq + j) * 2));
                    *(__nv_bfloat162*)(smem + SA_HI + sw)     = hi01;
                    *(__nv_bfloat162*)(smem + SA_HI + sw + 4) = hi23;
                    *(__nv_bfloat162*)(smem + SA_LO + sw)     = lo01;
                    *(__nv_bfloat162*)(smem + SA_LO + sw + 4) = lo23;
                }
            }
            // ---- B load: 128 n-rows x 64 k (hi + lo) ----
#pragma unroll
            for (int it = 0; it < 4; it++) {
                int idx = it * 256 + tid;
                int r = idx >> 3, q = idx & 7;
                size_t goff = (size_t)(n0 + r) * K3 + wk0 + kc + q * 8;
                uint32_t db = SWZ((uint32_t)(r * 128 + q * 16));
                *(uint4*)(smem + SB_HI + db) = *(const uint4*)(g_Wc_hi + goff);
                *(uint4*)(smem + SB_LO + db) = *(const uint4*)(g_Wc_lo + goff);
            }
            __syncthreads();
            // ---- MMA: 4 k16 steps ----
#pragma unroll
            for (int ks = 0; ks < 4; ks++) {
                int kb = ks * 32;
                uint32_t aH[2][4], aL[2][4], bH[4][2], bL[4][2];
#pragma unroll
                for (int g = 0; g < 2; g++) {
                    uint32_t off = SWZ((uint32_t)((mbase + g * 16 + a_row) * 128
                                                  + kb + a_kb));
                    ldm_x4(aH[g], sb + SA_HI + off);
                    ldm_x4(aL[g], sb + SA_LO + off);
                }
#pragma unroll
                for (int g = 0; g < 2; g++) {
                    uint32_t off = SWZ((uint32_t)((nbase + g * 16 + b_row) * 128
                                                  + kb + b_kb));
                    uint32_t rH[4], rL[4];
                    ldm_x4(rH, sb + SB_HI + off);
                    ldm_x4(rL, sb + SB_LO + off);
                    bH[g * 2 + 0][0] = rH[0]; bH[g * 2 + 0][1] = rH[1];
                    bH[g * 2 + 1][0] = rH[2]; bH[g * 2 + 1][1] = rH[3];
                    bL[g * 2 + 0][0] = rL[0]; bL[g * 2 + 0][1] = rL[1];
                    bL[g * 2 + 1][0] = rL[2]; bL[g * 2 + 1][1] = rL[3];
                }
#pragma unroll
                for (int mg = 0; mg < 2; mg++)
#pragma unroll
                    for (int nf = 0; nf < 4; nf++) {
                        mma_bf16(acc[mg][nf], aH[mg], bH[nf]);
                        mma_bf16(acc[mg][nf], aL[mg], bH[nf]);
                        mma_bf16(acc[mg][nf], aH[mg], bL[nf]);
                    }
            }
        }
        // ---- epilogue: acc -> g_part[ksp] ----
#pragma unroll
        for (int mg = 0; mg < 2; mg++) {
            int r0 = mb * 64 + mbase + mg * 16 + (lane >> 2);
            int r1 = r0 + 8;
#pragma unroll
            for (int nf = 0; nf < 4; nf++) {
                int col = n0 + nbase + nf * 8 + (lane & 3) * 2;
                if (r0 < cnt)
                    *(float2*)(g_part + ((size_t)ksp * MAXPERLVL + r0) * G6 + col)
                        = make_float2(acc[mg][nf][0], acc[mg][nf][1]);
                if (r1 < cnt)
                    *(float2*)(g_part + ((size_t)ksp * MAXPERLVL + r1) * G6 + col)
                        = make_float2(acc[mg][nf][2], acc[mg][nf][3]);
            }
        }
    }
}

// -------------------- compose finalize: sum 6 partials + cell ---------------
__global__ __launch_bounds__(256) void compose_fin(int lvl,
                                                   const float* __restrict__ b_comp) {
    int cnt = g_lvlcnt[lvl];
    if (cnt > MAXPERLVL) cnt = MAXPERLVL;
    int total = cnt << 10;
    for (int idx = blockIdx.x * 256 + threadIdx.x; idx < total; idx += gridDim.x * 256) {
        int op = idx >> 10, jh = idx & (NH - 1);
        const int* rec = g_list + ((size_t)lvl * MAXPERLVL + op) * 4;
        int dst = rec[0], cX = rec[1], cL = rec[2], cR = rec[3];
        float a[6];
#pragma unroll
        for (int g = 0; g < 6; g++) {
            int n = g * NH + jh;
            float s = b_comp[n];
#pragma unroll
            for (int p = 0; p < NSPLIT; p++)
                s += g_part[((size_t)p * MAXPERLVL + op) * G6 + n];
            a[g] = s;
        }
        float cl = 0.f, cx = 0.f, cr = 0.f;
        if (cL >= 0) cl = (cL < 4096) ? g_cs[(size_t)cL * NH + jh]
                                      : g_nc[(size_t)(cL - 4096) * NH + jh];
        if (cX >= 0) cx = (cX < 4096) ? g_cs[(size_t)cX * NH + jh]
                                      : g_nc[(size_t)(cX - 4096) * NH + jh];
        if (cR >= 0) cr = (cR < 4096) ? g_cs[(size_t)cR * NH + jh]
                                      : g_nc[(size_t)(cR - 4096) * NH + jh];
        float c = sigf(a[0]) * tanhf(a[4]) + sigf(a[1]) * cl
                + sigf(a[2]) * cx + sigf(a[3]) * cr;
        float h = sigf(a[5]) * tanhf(c);
        g_nh[(size_t)dst * NH + jh] = h;
        g_nc[(size_t)dst * NH + jh] = c;
    }
}

// -------------------- gather roots into output ------------------------------
__global__ void gather_out(float* __restrict__ out) {
    int idx = blockIdx.x * blockDim.x + threadIdx.x;
    int b = idx >> 10, j = idx & (NH - 1);
    int code = g_root[b];
    float h = 0.f, c = 0.f;
    if (code >= 0) {
        if (code < 4096) {
            h = g_hs[(size_t)code * NH + j];
            c = g_cs[(size_t)code * NH + j];
        } else {
            int n = code - 4096;
            h = g_nh[(size_t)n * NH + j];
            c = g_nc[(size_t)n * NH + j];
        }
    }
    out[idx] = h;
    out[NB * NH + idx] = c;
}

// -------------------- launcher ---------------------------------------------
extern "C" void kernel_launch(void* const* d_in, const int* in_sizes, int n_in,
                              void* d_out, int out_size) {
    const float* x      = (const float*)d_in[0];
    const float* W_ih   = (const float*)d_in[1];
    const float* W_hh   = (const float*)d_in[2];
    const float* b_ih   = (const float*)d_in[3];
    const float* b_hh   = (const float*)d_in[4];
    const float* W_comp = (const float*)d_in[5];
    const float* b_comp = (const float*)d_in[6];
    const int*   words  = (const int*)d_in[7];
    const int*   lens   = (const int*)d_in[8];
    float* out = (float*)d_out;

    void* pWtIh = 0;
    cudaGetSymbolAddress(&pWtIh, g_WtIh);

    cudaFuncSetAttribute(compose_mma,
                         cudaFuncAttributeMaxDynamicSharedMemorySize, CSMEM);

    dim3 thr(32, 8);
    transposeK<<<dim3(128, 10), thr>>>(W_ih, (float*)pWtIh, G4, ND, KIH);
    transposeWhh<<<4096, 256>>>(W_hh);
    packWcomp<<<(int)(((size_t)G6 * K3 + 255) / 256), 256>>>(W_comp);

    xg_gemm<<<dim3(32, 32), 256>>>(x, b_ih, b_hh);

    schedule<<<1, 32>>>(words, lens);
    listbuild<<<1, 32>>>();

    for (int t = 0; t < NL; t++)
        lstm_step<<<128, thr>>>(t);

    for (int lvl = 1; lvl < MAXLVL; lvl++) {
        compose_mma<<<dim3(288, 16), 256, CSMEM>>>(lvl);
        compose_fin<<<256, 256>>>(lvl, b_comp);
    }

    gather_out<<<64, 512>>>(out);
}

// round 14
// speedup vs baseline: 3.9618x; 1.4981x over previous
#include <cuda_runtime.h>
#include <cuda_bf16.h>
#include <math.h>
#include <stdint.h>

#define NB 32
#define NL 128
#define ND 300
#define NH 1024
#define G4 4096
#define G6 6144
#define K3 3072
#define KIH 320
#define MAXLVL 48
#define MAXPERLVL 2048
#define NSPLIT 6

typedef unsigned long long u64;

// -------------------- f32x2 packed helpers (FFMA2 path) ---------------------
__device__ __forceinline__ u64 dup2(float x) {
    u64 r; asm("mov.b64 %0, {%1, %1};" : "=l"(r) : "f"(x)); return r;
}
__device__ __forceinline__ u64 pack2(float x, float y) {
    u64 r; asm("mov.b64 %0, {%1, %2};" : "=l"(r) : "f"(x), "f"(y)); return r;
}
__device__ __forceinline__ void ffma2(u64& d, u64 a, u64 b) {
    asm("fma.rn.f32x2 %0, %1, %2, %3;" : "=l"(d) : "l"(a), "l"(b), "l"(d));
}
__device__ __forceinline__ float2 unpk2(u64 v) {
    float2 f; asm("mov.b64 {%0, %1}, %2;" : "=f"(f.x), "=f"(f.y) : "l"(v)); return f;
}
__device__ __forceinline__ float sigf(float x) { return 1.f / (1.f + expf(-x)); }

// -------------------- legacy tensor-core helpers (compute_103-safe) ---------
__device__ __forceinline__ uint32_t smem_u32(const void* p) {
    return (uint32_t)__cvta_generic_to_shared(p);
}
__device__ __forceinline__ void ldm_x4(uint32_t* r, uint32_t addr) {
    asm volatile("ldmatrix.sync.aligned.m8n8.x4.shared.b16 {%0,%1,%2,%3}, [%4];"
        : "=r"(r[0]), "=r"(r[1]), "=r"(r[2]), "=r"(r[3]) : "r"(addr));
}
__device__ __forceinline__ void mma_bf16(float* c, const uint32_t* a, const uint32_t* b) {
    asm volatile("mma.sync.aligned.m16n8k16.row.col.f32.bf16.bf16.f32 "
        "{%0,%1,%2,%3}, {%4,%5,%6,%7}, {%8,%9}, {%0,%1,%2,%3};"
        : "+f"(c[0]), "+f"(c[1]), "+f"(c[2]), "+f"(c[3])
        : "r"(a[0]), "r"(a[1]), "r"(a[2]), "r"(a[3]), "r"(b[0]), "r"(b[1]));
}
#define SWZ(b) ((b) ^ (((b) >> 3) & 0x70))

// -------------------- scratch (device globals) ------------------------------
__device__ float g_WtIh[KIH * G4];
__device__ __nv_bfloat16 g_Wc_hi[(size_t)G6 * K3];   // [n][k]
__device__ __nv_bfloat16 g_Wc_lo[(size_t)G6 * K3];
__device__ __nv_bfloat16 g_Whh_hi[(size_t)G4 * NH];  // [n'=jh*4+gate][k]
__device__ __nv_bfloat16 g_Whh_lo[(size_t)G4 * NH];
__device__ __nv_bfloat16 g_hA_hi[NB * NH];           // h_{t-1} bf16 hi [b][k]
__device__ __nv_bfloat16 g_hA_lo[NB * NH];
__device__ float g_Xg[(NB * NL) * G4];
__device__ float g_hs[NB * NL * NH];
__device__ float g_cs[NB * NL * NH];
__device__ float g_nh[NB * NL * NH];
__device__ float g_nc[NB * NL * NH];
__device__ float g_part[(size_t)NSPLIT * MAXPERLVL * G6];
__device__ int   g_ops[NB * NL * 4];
__device__ int   g_nops[NB];
__device__ int   g_root[NB];
__device__ int   g_lvlcnt[MAXLVL];
__device__ int   g_list[MAXLVL * MAXPERLVL * 4];

// -------------------- transpose W[N][K] -> Wt[Kp][N] ------------------------
__global__ void transposeK(const float* __restrict__ W, float* __restrict__ Wt,
                           int N, int K, int Kp) {
    __shared__ float tile[32][33];
    int j0 = blockIdx.x * 32, k0 = blockIdx.y * 32;
    int tx = threadIdx.x, ty = threadIdx.y;
    for (int r = ty; r < 32; r += 8) {
        int j = j0 + r, k = k0 + tx;
        tile[r][tx] = (j < N && k < K) ? W[(size_t)j * K + k] : 0.f;
    }
    __syncthreads();
    for (int r = ty; r < 32; r += 8) {
        int k = k0 + r, j = j0 + tx;
        if (k < Kp && j < N) Wt[(size_t)k * N + j] = tile[tx][r];
    }
}

// -------------------- W_hh -> bf16 hi/lo, rows permuted n'=jh*4+gate --------
__global__ void packWhh(const float* __restrict__ W) {
    int row = blockIdx.x;                 // orig row = gate*1024 + jh
    int gate = row >> 10, jh = row & 1023;
    int rowp = (jh << 2) + gate;
    const float* src = W + (size_t)row * NH;
    for (int k = threadIdx.x; k < NH; k += 256) {
        float v = src[k];
        __nv_bfloat16 h = __float2bfloat16(v);
        g_Whh_hi[(size_t)rowp * NH + k] = h;
        g_Whh_lo[(size_t)rowp * NH + k] = __float2bfloat16(v - __bfloat162float(h));
    }
}

// -------------------- split W_comp into bf16 hi/lo (native [n][k]) ----------
__global__ void packWcomp(const float* __restrict__ W) {
    size_t i = (size_t)blockIdx.x * 256 + threadIdx.x;
    if (i < (size_t)G6 * K3) {
        float v = W[i];
        __nv_bfloat16 h = __float2bfloat16(v);
        g_Wc_hi[i] = h;
        g_Wc_lo[i] = __float2bfloat16(v - __bfloat162float(h));
    }
}

// -------------------- Xg = x @ WtIh + b_ih + b_hh (f32x2 sgemm) -------------
__global__ __launch_bounds__(256) void xg_gemm(const float* __restrict__ x,
                                               const float* __restrict__ b_ih,
                                               const float* __restrict__ b_hh) {
    __shared__ float As[16][132];
    __shared__ float Bs[16][128];
    int tid = threadIdx.x;
    int tx = tid & 15, ty = tid >> 4;
    int n0 = blockIdx.x * 128, m0 = blockIdx.y * 128;
    u64 acc[8][4];
#pragma unroll
    for (int i = 0; i < 8; i++)
#pragma unroll
        for (int q = 0; q < 4; q++) acc[i][q] = 0ull;

    for (int k0 = 0; k0 < KIH; k0 += 16) {
        __syncthreads();
        {
            int r = tid >> 1;
            int kb = (tid & 1) * 8;
            const float* xr = x + (size_t)(m0 + r) * ND + k0 + kb;
#pragma unroll
            for (int i = 0; i < 8; i++) {
                int k = k0 + kb + i;
                As[kb + i][r] = (k < ND) ? xr[i] : 0.f;
            }
            int br = tid >> 4, bc = (tid & 15) * 8;
            const float* wb = g_WtIh + (size_t)(k0 + br) * G4 + n0 + bc;
            *(float4*)&Bs[br][bc]     = *(const float4*)(wb);
            *(float4*)&Bs[br][bc + 4] = *(const float4*)(wb + 4);
        }
        __syncthreads();
#pragma unroll
        for (int kk = 0; kk < 16; kk++) {
            float4 a0 = *(const float4*)&As[kk][ty * 4];
            float4 a1 = *(const float4*)&As[kk][64 + ty * 4];
            u64 ad[8] = {dup2(a0.x), dup2(a0.y), dup2(a0.z), dup2(a0.w),
                         dup2(a1.x), dup2(a1.y), dup2(a1.z), dup2(a1.w)};
            ulonglong2 bb0 = *(const ulonglong2*)&Bs[kk][tx * 4];
            ulonglong2 bb1 = *(const ulonglong2*)&Bs[kk][64 + tx * 4];
#pragma unroll
            for (int i = 0; i < 8; i++) {
                ffma2(acc[i][0], ad[i], bb0.x);
                ffma2(acc[i][1], ad[i], bb0.y);
                ffma2(acc[i][2], ad[i], bb1.x);
                ffma2(acc[i][3], ad[i], bb1.y);
            }
        }
    }
#pragma unroll
    for (int hm = 0; hm < 2; hm++)
#pragma unroll
        for (int i = 0; i < 4; i++) {
            int m = m0 + hm * 64 + ty * 4 + i;
            float* orow = g_Xg + (size_t)m * G4 + n0;
#pragma unroll
            for (int hn = 0; hn < 2; hn++) {
                int nb = hn * 64 + tx * 4;
                float2 p0 = unpk2(acc[hm * 4 + i][hn * 2 + 0]);
                float2 p1 = unpk2(acc[hm * 4 + i][hn * 2 + 1]);
                float4 v;
                v.x = p0.x + b_ih[n0 + nb + 0] + b_hh[n0 + nb + 0];
                v.y = p0.y + b_ih[n0 + nb + 1] + b_hh[n0 + nb + 1];
                v.z = p1.x + b_ih[n0 + nb + 2] + b_hh[n0 + nb + 2];
                v.w = p1.y + b_ih[n0 + nb + 3] + b_hh[n0 + nb + 3];
                *(float4*)&orow[nb] = v;
            }
        }
}

// -------------------- LSTM step on tensor cores (bf16 3-pass) ---------------
// grid 64 blocks: block covers 64 n' cols = 16 jh (all 4 gates). M=32 batch,
// K=1024 in 16 chunks of 64, register-staged prefetch. Epilogue fuses cell.
#define LA_HI 0
#define LA_LO 4096
#define LB_HI 8192
#define LB_LO 16384
#define LSM   24576

__global__ __launch_bounds__(256) void lstm_mma(int t) {
    __shared__ __align__(128) char smem_l[LSM];
    uint32_t sb = smem_u32(smem_l);
    int tid = threadIdx.x;
    int lane = tid & 31, wid = tid >> 5;
    int mg = wid >> 2;            // 0..1 : rows 0-15 / 16-31
    int ng = wid & 3;             // 0..3 : n16 group
    int n0 = blockIdx.x * 64;

    float acc[2][4];
#pragma unroll
    for (int f = 0; f < 2; f++)
#pragma unroll
        for (int q = 0; q < 4; q++) acc[f][q] = 0.f;

    if (t > 0) {
        int a_row = (lane & 7) + ((lane >> 3) & 1) * 8;
        int a_kb  = (lane >> 4) * 16;
        int b_row = (lane & 7) + ((lane >> 4) & 1) * 8;
        int b_kb  = ((lane >> 3) & 1) * 16;

        int ar = tid >> 3, aq = tid & 7;
        const __nv_bfloat16* pAh = g_hA_hi + ar * NH + aq * 8;
        const __nv_bfloat16* pAl = g_hA_lo + ar * NH + aq * 8;
        int br0 = ar, br1 = ar + 32;
        const __nv_bfloat16* pBh0 = g_Whh_hi + (size_t)(n0 + br0) * NH + aq * 8;
        const __nv_bfloat16* pBh1 = g_Whh_hi + (size_t)(n0 + br1) * NH + aq * 8;
        const __nv_bfloat16* pBl0 = g_Whh_lo + (size_t)(n0 + br0) * NH + aq * 8;
        const __nv_bfloat16* pBl1 = g_Whh_lo + (size_t)(n0 + br1) * NH + aq * 8;
        uint32_t dA  = SWZ((uint32_t)(ar * 128 + aq * 16));
        uint32_t dB0 = SWZ((uint32_t)(br0 * 128 + aq * 16));
        uint32_t dB1 = SWZ((uint32_t)(br1 * 128 + aq * 16));

        uint4 rAh = *(const uint4*)(pAh);
        uint4 rAl = *(const uint4*)(pAl);
        uint4 rBh0 = *(const uint4*)(pBh0);
        uint4 rBh1 = *(const uint4*)(pBh1);
        uint4 rBl0 = *(const uint4*)(pBl0);
        uint4 rBl1 = *(const uint4*)(pBl1);

        for (int ch = 0; ch < 16; ch++) {
            __syncthreads();
            *(uint4*)(smem_l + LA_HI + dA)  = rAh;
            *(uint4*)(smem_l + LA_LO + dA)  = rAl;
            *(uint4*)(smem_l + LB_HI + dB0) = rBh0;
            *(uint4*)(smem_l + LB_HI + dB1) = rBh1;
            *(uint4*)(smem_l + LB_LO + dB0) = rBl0;
            *(uint4*)(smem_l + LB_LO + dB1) = rBl1;
            __syncthreads();
            if (ch < 15) {
                int kc = (ch + 1) * 64;
                rAh  = *(const uint4*)(pAh + kc);
                rAl  = *(const uint4*)(pAl + kc);
                rBh0 = *(const uint4*)(pBh0 + kc);
                rBh1 = *(const uint4*)(pBh1 + kc);
                rBl0 = *(const uint4*)(pBl0 + kc);
                rBl1 = *(const uint4*)(pBl1 + kc);
            }
#pragma unroll
            for (int ks = 0; ks < 4; ks++) {
                int kb = ks * 32;
                uint32_t aH[4], aL[4], rH[4], rL[4];
                uint32_t offA = SWZ((uint32_t)((mg * 16 + a_row) * 128 + kb + a_kb));
                ldm_x4(aH, sb + LA_HI + offA);
                ldm_x4(aL, sb + LA_LO + offA);
                uint32_t offB = SWZ((uint32_t)((ng * 16 + b_row) * 128 + kb + b_kb));
                ldm_x4(rH, sb + LB_HI + offB);
                ldm_x4(rL, sb + LB_LO + offB);
                uint32_t bH0[2] = {rH[0], rH[1]}, bH1[2] = {rH[2], rH[3]};
                uint32_t bL0[2] = {rL[0], rL[1]}, bL1[2] = {rL[2], rL[3]};
                mma_bf16(acc[0], aH, bH0);
                mma_bf16(acc[0], aL, bH0);
                mma_bf16(acc[0], aH, bL0);
                mma_bf16(acc[1], aH, bH1);
                mma_bf16(acc[1], aL, bH1);
                mma_bf16(acc[1], aH, bL1);
            }
        }
    }

    // ---- fused cell epilogue ----
    int r0 = mg * 16 + (lane >> 2);
#pragma unroll
    for (int nf = 0; nf < 2; nf++) {
        float p0 = __shfl_xor_sync(0xffffffffu, acc[nf][0], 1);
        float p1 = __shfl_xor_sync(0xffffffffu, acc[nf][1], 1);
        float p2 = __shfl_xor_sync(0xffffffffu, acc[nf][2], 1);
        float p3 = __shfl_xor_sync(0xffffffffu, acc[nf][3], 1);
        if ((lane & 1) == 0) {
            int np = n0 + ng * 16 + nf * 8 + (lane & 3) * 2;
            int jh = np >> 2;
#pragma unroll
            for (int rr = 0; rr < 2; rr++) {
                int b = r0 + rr * 8;
                float ai = rr ? acc[nf][2] : acc[nf][0];
                float af = rr ? acc[nf][3] : acc[nf][1];
                float ag = rr ? p2 : p0;
                float ao = rr ? p3 : p1;
                size_t xr = (size_t)(b * NL + t) * G4;
                float gi = ai + g_Xg[xr + jh];
                float gf = af + g_Xg[xr + NH + jh];
                float gg = ag + g_Xg[xr + 2 * NH + jh];
                float go = ao + g_Xg[xr + 3 * NH + jh];
                float cp = (t > 0) ? g_cs[(size_t)(b * NL + t - 1) * NH + jh] : 0.f;
                float c = sigf(gf) * cp + sigf(gi) * tanhf(gg);
                float h = sigf(go) * tanhf(c);
                g_hs[(size_t)(b * NL + t) * NH + jh] = h;
                g_cs[(size_t)(b * NL + t) * NH + jh] = c;
                __nv_bfloat16 hh = __float2bfloat16(h);
                g_hA_hi[b * NH + jh] = hh;
                g_hA_lo[b * NH + jh] = __float2bfloat16(h - __bfloat162float(hh));
            }
        }
    }
}

// -------------------- tree schedule: per-batch greedy build -----------------
__global__ void schedule(const int* __restrict__ words, const int* __restrict__ lens) {
    int b = threadIdx.x;
    for (int i = b; i < MAXLVL; i += 32) g_lvlcnt[i] = 0;
    if (b >= NB) return;
    int len = lens[b];
    if (len > NL) len = NL;
    if (len < 0) len = 0;
    int keys[NL];
    for (int l = 0; l < len; l++) keys[l] = words[b * NL + l] % 1000;
    int oplv[NL];
    int st_s[NL + 4], st_e[NL + 4], st_p[NL + 4], st_st[NL + 4], st_l[NL + 4];
    int sp = 0;
    st_s[0] = 0; st_e[0] = len; st_st[0] = 0; sp = 1;
    int ret = -1, nops = 0;
    while (sp > 0) {
        int i = sp - 1;
        int stage = st_st[i];
        if (stage == 0) {
            int s = st_s[i], e = st_e[i];
            if (e <= s)            { ret = -1; sp--; }
            else if (e == s + 1)   { ret = s;  sp--; }
            else {
                int bk = 0x7fffffff, bp = s;
                for (int l = s; l < e; l++)
                    if (keys[l] < bk) { bk = keys[l]; bp = l; }
                st_p[i] = bp; st_st[i] = 1;
                st_s[sp] = s; st_e[sp] = bp; st_st[sp] = 0; sp++;
            }
        } else if (stage == 1) {
            st_l[i] = ret; st_st[i] = 2;
            st_s[sp] = st_p[i] + 1; st_e[sp] = st_e[i]; st_st[sp] = 0; sp++;
        } else {
            int li = st_l[i], ri = ret;
            int ll = (li >= 1000) ? oplv[li - 1000] : 0;
            int rl = (ri >= 1000) ? oplv[ri - 1000] : 0;
            int lvl = 1 + (ll > rl ? ll : rl);
            int idx = nops++;
            oplv[idx] = lvl;
            int base = (b * NL + idx) * 4;
            g_ops[base + 0] = st_p[i];
            g_ops[base + 1] = li;
            g_ops[base + 2] = ri;
            g_ops[base + 3] = lvl;
            ret = 1000 + idx; sp--;
        }
    }
    g_nops[b] = nops;
    int root;
    if (ret >= 1000)      root = 4096 + b * NL + (ret - 1000);
    else if (ret >= 0)    root = b * NL + ret;
    else                  root = -1;
    g_root[b] = root;
}

// -------------------- bucket ops into per-level work lists ------------------
__global__ void listbuild() {
    int b = threadIdx.x;
    if (b >= NB) return;
    int n = g_nops[b];
    for (int i = 0; i < n; i++) {
        int base = (b * NL + i) * 4;
        int xp  = g_ops[base + 0];
        int li  = g_ops[base + 1];
        int ri  = g_ops[base + 2];
        int lvl = g_ops[base + 3];
        if (lvl >= MAXLVL) lvl = MAXLVL - 1;
        int slot = atomicAdd(&g_lvlcnt[lvl], 1);
        if (slot < MAXPERLVL) {
            int lb = (lvl * MAXPERLVL + slot) * 4;
            g_list[lb + 0] = b * NL + i;
            g_list[lb + 1] = b * NL + xp;
            g_list[lb + 2] = (li < 0) ? -1 : (li < 1000 ? b * NL + li
                                                        : 4096 + b * NL + (li - 1000));
            g_list[lb + 3] = (ri < 0) ? -1 : (ri < 1000 ? b * NL + ri
                                                        : 4096 + b * NL + (ri - 1000));
        }
    }
}

// -------------------- compose via mma.sync bf16 3-pass split ----------------
#define SA_HI 0
#define SA_LO 8192
#define SB_HI 16384
#define SB_LO 32768
#define SM_CH 49152
#define CSMEM 49408

__global__ void __launch_bounds__(256) compose_mma(int lvl) {
    int cnt = g_lvlcnt[lvl];
    if (cnt > MAXPERLVL) cnt = MAXPERLVL;
    if (cnt == 0) return;
    int mtiles = (cnt + 63) >> 6;
    if ((int)blockIdx.y >= mtiles) return;
    int ksp = blockIdx.x % 6;
    int n0 = (blockIdx.x / 6) * 128;
    int seg = ksp >> 1, khalf = ksp & 1;
    int hoff = khalf * 512;
    int wk0 = seg * NH + khalf * 512;

    extern __shared__ char smem[];
    uint32_t sb = smem_u32(smem);
    int* s_ch = (int*)(smem + SM_CH);
    int tid = threadIdx.x;
    int lane = tid & 31, wid = tid >> 5;
    int mbase = (wid >> 2) * 32;
    int nbase = (wid & 3) * 32;

    int a_row = (lane & 7) + ((lane >> 3) & 1) * 8;
    int a_kb  = (lane >> 4) * 16;
    int b_row = (lane & 7) + ((lane >> 4) & 1) * 8;
    int b_kb  = ((lane >> 3) & 1) * 16;

    for (int mb = blockIdx.y; mb < mtiles; mb += 16) {
        __syncthreads();
        if (tid < 64) {
            int op = mb * 64 + tid;
            if (op > cnt - 1) op = cnt - 1;
            const int* rec = g_list + ((size_t)lvl * MAXPERLVL + op) * 4;
            s_ch[tid] = (seg == 0) ? rec[2] : ((seg == 1) ? rec[1] : rec[3]);
        }
        __syncthreads();

        float acc[2][4][4];
#pragma unroll
        for (int i = 0; i < 2; i++)
#pragma unroll
            for (int j = 0; j < 4; j++)
#pragma unroll
                for (int q = 0; q < 4; q++) acc[i][j][q] = 0.f;

        for (int ch = 0; ch < 8; ch++) {
            int kc = ch * 64;
            __syncthreads();
            {
                int r = tid >> 2, kq = (tid & 3) * 16;
                int code = s_ch[r];
                const float* hp = 0;
                if (code >= 0)
                    hp = (code < 4096) ? (g_hs + (size_t)code * NH)
                                       : (g_nh + (size_t)(code - 4096) * NH);
#pragma unroll
                for (int j = 0; j < 16; j += 4) {
                    float4 v = (code >= 0)
                        ? *(const float4*)(hp + hoff + kc + kq + j)
                        : make_float4(0.f, 0.f, 0.f, 0.f);
                    __nv_bfloat16 hx = __float2bfloat16(v.x);
                    __nv_bfloat16 hy = __float2bfloat16(v.y);
                    __nv_bfloat16 hz = __float2bfloat16(v.z);
                    __nv_bfloat16 hw = __float2bfloat16(v.w);
                    __nv_bfloat162 hi01, hi23, lo01, lo23;
                    hi01.x = hx; hi01.y = hy; hi23.x = hz; hi23.y = hw;
                    lo01.x = __float2bfloat16(v.x - __bfloat162float(hx));
                    lo01.y = __float2bfloat16(v.y - __bfloat162float(hy));
                    lo23.x = __float2bfloat16(v.z - __bfloat162float(hz));
                    lo23.y = __float2bfloat16(v.w - __bfloat162float(hw));
                    uint32_t sw = SWZ((uint32_t)(r * 128 + (kq + j) * 2));
                    *(__nv_bfloat162*)(smem + SA_HI + sw)     = hi01;
                    *(__nv_bfloat162*)(smem + SA_HI + sw + 4) = hi23;
                    *(__nv_bfloat162*)(smem + SA_LO + sw)     = lo01;
                    *(__nv_bfloat162*)(smem + SA_LO + sw + 4) = lo23;
                }
            }
#pragma unroll
            for (int it = 0; it < 4; it++) {
                int idx = it * 256 + tid;
                int r = idx >> 3, q = idx & 7;
                size_t goff = (size_t)(n0 + r) * K3 + wk0 + kc + q * 8;
                uint32_t db = SWZ((uint32_t)(r * 128 + q * 16));
                *(uint4*)(smem + SB_HI + db) = *(const uint4*)(g_Wc_hi + goff);
                *(uint4*)(smem + SB_LO + db) = *(const uint4*)(g_Wc_lo + goff);
            }
            __syncthreads();
#pragma unroll
            for (int ks = 0; ks < 4; ks++) {
                int kb = ks * 32;
                uint32_t aH[2][4], aL[2][4], bH[4][2], bL[4][2];
#pragma unroll
                for (int g = 0; g < 2; g++) {
                    uint32_t off = SWZ((uint32_t)((mbase + g * 16 + a_row) * 128
                                                  + kb + a_kb));
                    ldm_x4(aH[g], sb + SA_HI + off);
                    ldm_x4(aL[g], sb + SA_LO + off);
                }
#pragma unroll
                for (int g = 0; g < 2; g++) {
                    uint32_t off = SWZ((uint32_t)((nbase + g * 16 + b_row) * 128
                                                  + kb + b_kb));
                    uint32_t rH[4], rL[4];
                    ldm_x4(rH, sb + SB_HI + off);
                    ldm_x4(rL, sb + SB_LO + off);
                    bH[g * 2 + 0][0] = rH[0]; bH[g * 2 + 0][1] = rH[1];
                    bH[g * 2 + 1][0] = rH[2]; bH[g * 2 + 1][1] = rH[3];
                    bL[g * 2 + 0][0] = rL[0]; bL[g * 2 + 0][1] = rL[1];
                    bL[g * 2 + 1][0] = rL[2]; bL[g * 2 + 1][1] = rL[3];
                }
#pragma unroll
                for (int mg = 0; mg < 2; mg++)
#pragma unroll
                    for (int nf = 0; nf < 4; nf++) {
                        mma_bf16(acc[mg][nf], aH[mg], bH[nf]);
                        mma_bf16(acc[mg][nf], aL[mg], bH[nf]);
                        mma_bf16(acc[mg][nf], aH[mg], bL[nf]);
                    }
            }
        }
#pragma unroll
        for (int mg = 0; mg < 2; mg++) {
            int r0 = mb * 64 + mbase + mg * 16 + (lane >> 2);
            int r1 = r0 + 8;
#pragma unroll
            for (int nf = 0; nf < 4; nf++) {
                int col = n0 + nbase + nf * 8 + (lane & 3) * 2;
                if (r0 < cnt)
                    *(float2*)(g_part + ((size_t)ksp * MAXPERLVL + r0) * G6 + col)
                        = make_float2(acc[mg][nf][0], acc[mg][nf][1]);
                if (r1 < cnt)
                    *(float2*)(g_part + ((size_t)ksp * MAXPERLVL + r1) * G6 + col)
                        = make_float2(acc[mg][nf][2], acc[mg][nf][3]);
            }
        }
    }
}

// -------------------- compose finalize: sum 6 partials + cell ---------------
__global__ __launch_bounds__(256) void compose_fin(int lvl,
                                                   const float* __restrict__ b_comp) {
    int cnt = g_lvlcnt[lvl];
    if (cnt > MAXPERLVL) cnt = MAXPERLVL;
    int total = cnt << 10;
    for (int idx = blockIdx.x * 256 + threadIdx.x; idx < total; idx += gridDim.x * 256) {
        int op = idx >> 10, jh = idx & (NH - 1);
        const int* rec = g_list + ((size_t)lvl * MAXPERLVL + op) * 4;
        int dst = rec[0], cX = rec[1], cL = rec[2], cR = rec[3];
        float a[6];
#pragma unroll
        for (int g = 0; g < 6; g++) {
            int n = g * NH + jh;
            float s = b_comp[n];
#pragma unroll
            for (int p = 0; p < NSPLIT; p++)
                s += g_part[((size_t)p * MAXPERLVL + op) * G6 + n];
            a[g] = s;
        }
        float cl = 0.f, cx = 0.f, cr = 0.f;
        if (cL >= 0) cl = (cL < 4096) ? g_cs[(size_t)cL * NH + jh]
                                      : g_nc[(size_t)(cL - 4096) * NH + jh];
        if (cX >= 0) cx = (cX < 4096) ? g_cs[(size_t)cX * NH + jh]
                                      : g_nc[(size_t)(cX - 4096) * NH + jh];
        if (cR >= 0) cr = (cR < 4096) ? g_cs[(size_t)cR * NH + jh]
                                      : g_nc[(size_t)(cR - 4096) * NH + jh];
        float c = sigf(a[0]) * tanhf(a[4]) + sigf(a[1]) * cl
                + sigf(a[2]) * cx + sigf(a[3]) * cr;
        float h = sigf(a[5]) * tanhf(c);
        g_nh[(size_t)dst * NH + jh] = h;
        g_nc[(size_t)dst * NH + jh] = c;
    }
}

// -------------------- gather roots into output ------------------------------
__global__ void gather_out(float* __restrict__ out) {
    int idx = blockIdx.x * blockDim.x + threadIdx.x;
    int b = idx >> 10, j = idx & (NH - 1);
    int code = g_root[b];
    float h = 0.f, c = 0.f;
    if (code >= 0) {
        if (code < 4096) {
            h = g_hs[(size_t)code * NH + j];
            c = g_cs[(size_t)code * NH + j];
        } else {
            int n = code - 4096;
            h = g_nh[(size_t)n * NH + j];
            c = g_nc[(size_t)n * NH + j];
        }
    }
    out[idx] = h;
    out[NB * NH + idx] = c;
}

// -------------------- launcher ---------------------------------------------
extern "C" void kernel_launch(void* const* d_in, const int* in_sizes, int n_in,
                              void* d_out, int out_size) {
    const float* x      = (const float*)d_in[0];
    const float* W_ih   = (const float*)d_in[1];
    const float* W_hh   = (const float*)d_in[2];
    const float* b_ih   = (const float*)d_in[3];
    const float* b_hh   = (const float*)d_in[4];
    const float* W_comp = (const float*)d_in[5];
    const float* b_comp = (const float*)d_in[6];
    const int*   words  = (const int*)d_in[7];
    const int*   lens   = (const int*)d_in[8];
    float* out = (float*)d_out;

    void* pWtIh = 0;
    cudaGetSymbolAddress(&pWtIh, g_WtIh);

    cudaFuncSetAttribute(compose_mma,
                         cudaFuncAttributeMaxDynamicSharedMemorySize, CSMEM);

    dim3 thr(32, 8);
    transposeK<<<dim3(128, 10), thr>>>(W_ih, (float*)pWtIh, G4, ND, KIH);
    packWhh<<<4096, 256>>>(W_hh);
    packWcomp<<<(int)(((size_t)G6 * K3 + 255) / 256), 256>>>(W_comp);

    xg_gemm<<<dim3(32, 32), 256>>>(x, b_ih, b_hh);

    schedule<<<1, 32>>>(words, lens);
    listbuild<<<1, 32>>>();

    for (int t = 0; t < NL; t++)
        lstm_mma<<<64, 256>>>(t);

    for (int lvl = 1; lvl < MAXLVL; lvl++) {
        compose_mma<<<dim3(288, 16), 256, CSMEM>>>(lvl);
        compose_fin<<<256, 256>>>(lvl, b_comp);
    }

    gather_out<<<64, 512>>>(out);
}